// round 5
// baseline (speedup 1.0000x reference)
#include <cuda_runtime.h>
#include <math.h>

#define M 4096
#define CN 64
#define BNEPS 1e-5

typedef unsigned long long u64;

// ---------------- packed f32x2 helpers ----------------------------------------
__device__ __forceinline__ u64 pk(float lo, float hi) {
    u64 r; asm("mov.b64 %0,{%1,%2};" : "=l"(r) : "f"(lo), "f"(hi)); return r;
}
__device__ __forceinline__ void upk(u64 v, float& lo, float& hi) {
    asm("mov.b64 {%0,%1},%2;" : "=f"(lo), "=f"(hi) : "l"(v));
}
__device__ __forceinline__ u64 ffma2(u64 a, u64 b, u64 c) {
    u64 d; asm("fma.rn.f32x2 %0,%1,%2,%3;" : "=l"(d) : "l"(a), "l"(b), "l"(c)); return d;
}

// ---------------- constant-memory weights (uniform-const port, no crossbar) ---
__constant__ __align__(16) float c_wr[320];    // w_rank [32][10]
__constant__ __align__(16) float c_br[32];
__constant__ __align__(16) float c_wh1[1024];  // w_h1 [32][32]
__constant__ __align__(16) float c_bh1[32];
__constant__ __align__(16) float c_wh2[512];   // w_h2 [16][32]
__constant__ __align__(16) float c_bh2[16];

// ---------------- scratch (device globals; no allocs allowed) ----------------
__device__ float g_table[5*16*64*16];                 // 320 KB
__device__ float g_bn0s1[CN], g_bn0s2[CN];
__device__ float g_bn1s[CN],  g_bn1q[CN];
__device__ float g_bn2s[CN],  g_bn2q[CN];
__device__ float g_scale0[CN], g_shift0[CN], g_u0[CN];
__device__ float g_base_r[CN*32];
__device__ float g_rc3[CN*32];
__device__ float g_scale1[CN], g_shift1[CN];
__device__ float g_rc4[CN*16];
__device__ float g_scale2[CN], g_shift2[CN];
__device__ float g_outconst[16];
__device__ float g_r3[(size_t)CN*4*32*M];             // 128 MB, layout [c][h][o][m]
__device__ float g_r4[(size_t)CN*4*16*M];             // 64 MB,  layout [c][h][o][m]

// ---------------- ktable: sparse-conv lookup table (+ accumulator zeroing) ----
__global__ void ktable(const float* __restrict__ conv_w) {
    int idx = blockIdx.x*blockDim.x + threadIdx.x;
    if (blockIdx.x == 0 && threadIdx.x < CN) {
        int t = threadIdx.x;
        g_bn0s1[t]=0.f; g_bn0s2[t]=0.f;
        g_bn1s[t]=0.f;  g_bn1q[t]=0.f;
        g_bn2s[t]=0.f;  g_bn2q[t]=0.f;
    }
    if (idx >= 5*16*64*16) return;
    int hw = idx & 15, c = (idx>>4)&63, combo = (idx>>10)&15, i = idx>>14;
    int h = hw>>2, w = hw&3, r = combo>>2, s = combo&3;
    float v = 0.f;
    if (h <= r && w <= s) v = conv_w[c*125 + i*25 + (r-h)*5 + (s-w)];
    g_table[idx] = v;
}

// Per-block shared slice of the table for channel c: stab[i*256 + combo*16 + k]
__device__ __forceinline__ void load_stab(float* stab, int c, int t, int nt) {
    for (int idx = t; idx < 1280; idx += nt) {
        int i = idx >> 8, rem = idx & 255;
        stab[idx] = g_table[(i*16 + (rem>>4))*1024 + c*16 + (rem&15)];
    }
}

__device__ __forceinline__ void compute_a_s(int m, const int* __restrict__ x,
                                            const float* __restrict__ stab, float* a) {
#pragma unroll
    for (int k = 0; k < 16; k++) a[k] = 0.f;
#pragma unroll
    for (int i = 0; i < 5; i++) {
        int r = x[m*10 + 2*i]     & 3;
        int s = x[m*10 + 2*i + 1] & 3;
        const float4* tp = reinterpret_cast<const float4*>(stab + i*256 + (r*4+s)*16);
        float4 t0 = tp[0], t1 = tp[1], t2 = tp[2], t3 = tp[3];
        a[0]+=t0.x; a[1]+=t0.y; a[2]+=t0.z; a[3]+=t0.w;
        a[4]+=t1.x; a[5]+=t1.y; a[6]+=t1.z; a[7]+=t1.w;
        a[8]+=t2.x; a[9]+=t2.y; a[10]+=t2.z; a[11]+=t2.w;
        a[12]+=t3.x; a[13]+=t3.y; a[14]+=t3.z; a[15]+=t3.w;
    }
}

// ---------------- k1: BN0 raw sums over the varying 4x4 region ----------------
__global__ void __launch_bounds__(256) k1(const int* __restrict__ x) {
    __shared__ __align__(16) float stab[1280];
    __shared__ float red_s, red_q;
    int c  = blockIdx.y;
    int t  = threadIdx.x;
    load_stab(stab, c, t, 256);
    if (t == 0) { red_s = 0.f; red_q = 0.f; }
    __syncthreads();
    int m = blockIdx.x*256 + t;
    float a[16];
    compute_a_s(m, x, stab, a);
    float s = 0.f, q = 0.f;
#pragma unroll
    for (int k = 0; k < 16; k++) { s += a[k]; q += a[k]*a[k]; }
    for (int off = 16; off; off >>= 1) {
        s += __shfl_down_sync(0xffffffffu, s, off);
        q += __shfl_down_sync(0xffffffffu, q, off);
    }
    if ((t & 31) == 0) { atomicAdd(&red_s, s); atomicAdd(&red_q, q); }
    __syncthreads();
    if (t == 0) {
        atomicAdd(&g_bn0s1[c], red_s);
        atomicAdd(&g_bn0s2[c], red_q);
    }
}

// ---------------- k2: finalize BN0, const path through w_rank/w_h1 -----------
__global__ void __launch_bounds__(1024) k2(const float* __restrict__ conv_b,
                   const float* __restrict__ bn0_g, const float* __restrict__ bn0_b) {
    __shared__ float shW4[32], shWall[32], su0[64];
    __shared__ float sh_rc2[2048];
    int t = threadIdx.x;
    if (t < 64) {
        double n0   = (double)M * 110.0;
        double mu_a = (double)g_bn0s1[t] / n0;
        double var  = (double)g_bn0s2[t] / n0 - mu_a*mu_a;
        double cb   = (double)conv_b[t];
        double mean = cb + mu_a;
        double sc   = (double)bn0_g[t] / sqrt(var + BNEPS);
        double sh   = (double)bn0_b[t] - mean*sc;
        g_scale0[t] = (float)sc;
        g_shift0[t] = (float)sh;
        float u0    = fmaxf((float)(cb*sc + sh), 0.f);
        g_u0[t]     = u0;
        su0[t]      = u0;
    }
    if (t < 32) {
        float w4 = 0.f, wall = 0.f;
        for (int w = 0; w < 10; w++) { float v = c_wr[t*10+w]; wall += v; if (w >= 4) w4 += v; }
        shW4[t] = w4; shWall[t] = wall;
    }
    __syncthreads();
#pragma unroll
    for (int rep = 0; rep < 2; rep++) {
        int idx = t + rep*1024;
        int c = idx >> 5, o = idx & 31;
        float br = c_br[o];
        g_base_r[idx] = su0[c]*shW4[o] + br;
        sh_rc2[idx]   = fmaxf(su0[c]*shWall[o] + br, 0.f);
    }
    __syncthreads();
#pragma unroll
    for (int rep = 0; rep < 2; rep++) {
        int idx = t + rep*1024;
        int c = idx >> 5, o = idx & 31;
        float acc = c_bh1[o];
#pragma unroll
        for (int i = 0; i < 32; i++) acc += sh_rc2[c*32+i] * c_wh1[o*32+i];
        g_rc3[idx] = acc;
        float s = acc, q = acc*acc;
        for (int off = 16; off; off >>= 1) {
            s += __shfl_down_sync(0xffffffffu, s, off);
            q += __shfl_down_sync(0xffffffffu, q, off);
        }
        if (o == 0) {
            float k = (float)(M*7);
            g_bn1s[c] += k*s;
            g_bn1q[c] += k*q;
        }
    }
}

// ---------------- k3: fused bn0+relu -> w_rank+relu -> w_h1 -------------------
// Thread = (sample m, h-pair hp). Weights come from __constant__ (uniform-const
// port) so the smem crossbar only serves the table gather.
__global__ void __launch_bounds__(256, 3) k3(const int* __restrict__ x,
                                             const float* __restrict__ conv_b) {
    __shared__ __align__(16) float stab[1280];
    __shared__ float sbase[32];
    __shared__ float red_s, red_q;
    int c = blockIdx.y, t = threadIdx.x;
    load_stab(stab, c, t, 256);
    if (t < 32) sbase[t] = g_base_r[c*32 + t];
    if (t == 0) { red_s = 0.f; red_q = 0.f; }
    __syncthreads();

    int hp = t >> 7;                       // h-pair: rows {2hp, 2hp+1}
    int m  = blockIdx.x*128 + (t & 127);
    float sc0 = g_scale0[c];
    float pc0 = conv_b[c]*sc0 + g_shift0[c];

    // conv rows 2hp, 2hp+1 only (8 values)
    float a8[8];
#pragma unroll
    for (int k = 0; k < 8; k++) a8[k] = 0.f;
    const int2* xp = reinterpret_cast<const int2*>(x + m*10);
#pragma unroll
    for (int i = 0; i < 5; i++) {
        int2 cd = xp[i];
        const float4* tp = reinterpret_cast<const float4*>(
            stab + i*256 + ((cd.x & 3)*4 + (cd.y & 3))*16 + hp*8);
        float4 t0 = tp[0], t1 = tp[1];
        a8[0]+=t0.x; a8[1]+=t0.y; a8[2]+=t0.z; a8[3]+=t0.w;
        a8[4]+=t1.x; a8[5]+=t1.y; a8[6]+=t1.z; a8[7]+=t1.w;
    }
#pragma unroll
    for (int k = 0; k < 8; k++) a8[k] = fmaxf(a8[k]*sc0 + pc0, 0.f);   // bn0 + relu

    // w_rank stage (scalar, const weights), output packed i-adjacent
    u64 r2p0[16], r2p1[16];
#pragma unroll
    for (int hh = 0; hh < 2; hh++) {
        float b0 = a8[hh*4+0], b1 = a8[hh*4+1], b2 = a8[hh*4+2], b3 = a8[hh*4+3];
#pragma unroll
        for (int oo = 0; oo < 16; oo++) {
            float e0 = sbase[2*oo],   e1 = sbase[2*oo+1];
            e0 += b0*c_wr[(2*oo)*10+0];   e1 += b0*c_wr[(2*oo+1)*10+0];
            e0 += b1*c_wr[(2*oo)*10+1];   e1 += b1*c_wr[(2*oo+1)*10+1];
            e0 += b2*c_wr[(2*oo)*10+2];   e1 += b2*c_wr[(2*oo+1)*10+2];
            e0 += b3*c_wr[(2*oo)*10+3];   e1 += b3*c_wr[(2*oo+1)*10+3];
            u64 r = pk(fmaxf(e0, 0.f), fmaxf(e1, 0.f));
            if (hh == 0) r2p0[oo] = r; else r2p1[oo] = r;
        }
    }

    // w_h1 stage: const weights (rows are i-contiguous -> natural 16B pairs)
    float s = 0.f, q = 0.f;
    size_t base0 = (size_t)((c*4 + 2*hp)*32)*M + m;   // row (c,h0,o=0)
#pragma unroll 4
    for (int o = 0; o < 32; o++) {
        u64 acc0 = pk(c_bh1[o], 0.f), acc1 = acc0;
        const ulonglong2* wp = reinterpret_cast<const ulonglong2*>(&c_wh1[o*32]);
#pragma unroll
        for (int i = 0; i < 8; i++) {
            ulonglong2 w2 = wp[i];
            acc0 = ffma2(r2p0[2*i],   w2.x, acc0);
            acc0 = ffma2(r2p0[2*i+1], w2.y, acc0);
            acc1 = ffma2(r2p1[2*i],   w2.x, acc1);
            acc1 = ffma2(r2p1[2*i+1], w2.y, acc1);
        }
        float l0, h0, l1, h1;
        upk(acc0, l0, h0); upk(acc1, l1, h1);
        float v0 = l0 + h0, v1 = l1 + h1;
        s += v0 + v1;
        q += v0*v0 + v1*v1;
        g_r3[base0 + (size_t)o*M]        = v0;
        g_r3[base0 + (size_t)(o + 32)*M] = v1;       // h0+1 row
    }
    for (int off = 16; off; off >>= 1) {
        s += __shfl_down_sync(0xffffffffu, s, off);
        q += __shfl_down_sync(0xffffffffu, q, off);
    }
    if ((t & 31) == 0) { atomicAdd(&red_s, s); atomicAdd(&red_q, q); }
    __syncthreads();
    if (t == 0) { atomicAdd(&g_bn1s[c], red_s); atomicAdd(&g_bn1q[c], red_q); }
}

// ---------------- k4: finalize BN1, const path through w_h2 -------------------
__global__ void __launch_bounds__(1024) k4(const float* __restrict__ bn1_g,
                                           const float* __restrict__ bn1_b) {
    __shared__ float rc3bn[2048];
    __shared__ float ssc[64], ssh[64];
    int t = threadIdx.x;
    if (t < 64) {
        double n1   = (double)M * 11.0 * 32.0;
        double mean = (double)g_bn1s[t] / n1;
        double var  = (double)g_bn1q[t] / n1 - mean*mean;
        double sc   = (double)bn1_g[t] / sqrt(var + BNEPS);
        double sh   = (double)bn1_b[t] - mean*sc;
        g_scale1[t] = (float)sc;  ssc[t] = (float)sc;
        g_shift1[t] = (float)sh;  ssh[t] = (float)sh;
    }
    __syncthreads();
#pragma unroll
    for (int rep = 0; rep < 2; rep++) {
        int idx = t + rep*1024;
        int c = idx >> 5;
        rc3bn[idx] = fmaxf(g_rc3[idx]*ssc[c] + ssh[c], 0.f);
    }
    __syncthreads();
    {
        int c = t >> 4, o = t & 15;
        float acc = c_bh2[o];
#pragma unroll
        for (int i = 0; i < 32; i++) acc += rc3bn[c*32+i] * c_wh2[o*32+i];
        g_rc4[t] = acc;
        float s = acc, q = acc*acc;
        for (int off = 8; off; off >>= 1) {
            s += __shfl_down_sync(0xffffffffu, s, off, 16);
            q += __shfl_down_sync(0xffffffffu, q, off, 16);
        }
        if (o == 0) {
            float k = (float)(M*7);
            g_bn2s[c] += k*s;
            g_bn2q[c] += k*q;
        }
    }
}

// ---------------- k5: fused bn1+relu -> w_h2, BN2 sums ------------------------
// Thread = (sample m, h-pair). Const weights, no smem staging at all.
__global__ void __launch_bounds__(256, 3) k5() {
    __shared__ float red_s, red_q;
    int c = blockIdx.y, t = threadIdx.x;
    if (t == 0) { red_s = 0.f; red_q = 0.f; }
    __syncthreads();

    int hp = t >> 7;
    int m  = blockIdx.x*128 + (t & 127);
    float sc1 = g_scale1[c], sf1 = g_shift1[c];

    // load + bn1 + relu for both h rows, i-adjacent packed
    u64 yp0[16], yp1[16];
    size_t rbase = (size_t)((c*4 + 2*hp)*32)*M + m;
#pragma unroll
    for (int i2 = 0; i2 < 16; i2++) {
        float v0 = g_r3[rbase + (size_t)(2*i2)*M];
        float v1 = g_r3[rbase + (size_t)(2*i2+1)*M];
        yp0[i2] = pk(fmaxf(v0*sc1 + sf1, 0.f), fmaxf(v1*sc1 + sf1, 0.f));
    }
#pragma unroll
    for (int i2 = 0; i2 < 16; i2++) {
        float v0 = g_r3[rbase + (size_t)(32 + 2*i2)*M];
        float v1 = g_r3[rbase + (size_t)(32 + 2*i2+1)*M];
        yp1[i2] = pk(fmaxf(v0*sc1 + sf1, 0.f), fmaxf(v1*sc1 + sf1, 0.f));
    }

    float s = 0.f, q = 0.f;
    size_t wbase = (size_t)((c*4 + 2*hp)*16)*M + m;
#pragma unroll 4
    for (int o = 0; o < 16; o++) {
        u64 acc0 = pk(c_bh2[o], 0.f), acc1 = acc0;
        const ulonglong2* wp = reinterpret_cast<const ulonglong2*>(&c_wh2[o*32]);
#pragma unroll
        for (int i = 0; i < 8; i++) {
            ulonglong2 w2 = wp[i];
            acc0 = ffma2(yp0[2*i],   w2.x, acc0);
            acc0 = ffma2(yp0[2*i+1], w2.y, acc0);
            acc1 = ffma2(yp1[2*i],   w2.x, acc1);
            acc1 = ffma2(yp1[2*i+1], w2.y, acc1);
        }
        float l0, h0, l1, h1;
        upk(acc0, l0, h0); upk(acc1, l1, h1);
        float v0 = l0 + h0, v1 = l1 + h1;
        s += v0 + v1;
        q += v0*v0 + v1*v1;
        g_r4[wbase + (size_t)o*M]        = v0;
        g_r4[wbase + (size_t)(o + 16)*M] = v1;
    }
    for (int off = 16; off; off >>= 1) {
        s += __shfl_down_sync(0xffffffffu, s, off);
        q += __shfl_down_sync(0xffffffffu, q, off);
    }
    if ((t & 31) == 0) { atomicAdd(&red_s, s); atomicAdd(&red_q, q); }
    __syncthreads();
    if (t == 0) { atomicAdd(&g_bn2s[c], red_s); atomicAdd(&g_bn2q[c], red_q); }
}

// ---------------- k6: finalize BN2, constant-row output contribution ----------
__global__ void k6(const float* __restrict__ bn2_g, const float* __restrict__ bn2_b,
                   const float* __restrict__ w_out, const float* __restrict__ b_out) {
    __shared__ float rc5[64*16];
    int t = threadIdx.x;                              // 288 = 9 warps
    if (t < 64) {
        double n2   = (double)M * 11.0 * 16.0;
        double mean = (double)g_bn2s[t] / n2;
        double var  = (double)g_bn2q[t] / n2 - mean*mean;
        double sc   = (double)bn2_g[t] / sqrt(var + BNEPS);
        double sh   = (double)bn2_b[t] - mean*sc;
        g_scale2[t] = (float)sc;
        g_shift2[t] = (float)sh;
    }
    __syncthreads();
    for (int idx = t; idx < 1024; idx += 288) {
        int c = idx >> 4;
        rc5[idx] = fmaxf(g_rc4[idx]*g_scale2[c] + g_shift2[c], 0.f);
    }
    __syncthreads();
    int j = t >> 5, lane = t & 31;
    if (j < 9) {
        float acc = 0.f;
        for (int p = lane; p < 1024; p += 32) {
            int c = p >> 4, o = p & 15;
            float ws = 0.f;
#pragma unroll
            for (int h = 4; h < 11; h++) ws += w_out[j*11264 + c*176 + h*16 + o];
            acc += rc5[p]*ws;
        }
        for (int off = 16; off; off >>= 1) acc += __shfl_down_sync(0xffffffffu, acc, off);
        if (!lane) g_outconst[j] = b_out[j] + acc;
    }
}

// ---------------- k6b: seed output with constant part -------------------------
__global__ void k6b(float* __restrict__ out) {
    int idx = blockIdx.x*256 + threadIdx.x;
    if (idx < M*9) out[idx] = g_outconst[idx % 9];
}

// ---------------- k7: varying-feature GEMM (bn2+relu fused, f32x2 packed) -----
__global__ void __launch_bounds__(256) k7(const float* __restrict__ w_out,
                                          float* __restrict__ out) {
    __shared__ u64 sw[9*64];                          // duplicated-packed, 4.5 KB
    int t = threadIdx.x;
    int warp = t >> 5, lane = t & 31;
    int mbase = blockIdx.x*512 + warp*64 + lane*2;
    int c0 = blockIdx.y*2;
    u64 acc[9];
#pragma unroll
    for (int j = 0; j < 9; j++) acc[j] = 0;
    for (int cc = 0; cc < 2; cc++) {
        int c = c0 + cc;
        __syncthreads();
        for (int idx = t; idx < 576; idx += 256) {
            int j = idx / 64, qq = idx % 64;
            float w = w_out[j*11264 + c*176 + qq];
            sw[idx] = pk(w, w);
        }
        __syncthreads();
        float sc = g_scale2[c], sf = g_shift2[c];
        u64 scp = pk(sc, sc), sfp = pk(sf, sf);
        for (int qq = 0; qq < 64; qq++) {
            u64 v = *reinterpret_cast<const u64*>(&g_r4[(size_t)(c*64+qq)*M + mbase]);
            u64 y = ffma2(v, scp, sfp);
            float y0, y1; upk(y, y0, y1);
            y = pk(fmaxf(y0, 0.f), fmaxf(y1, 0.f));
#pragma unroll
            for (int j = 0; j < 9; j++) acc[j] = ffma2(y, sw[j*64+qq], acc[j]);
        }
    }
#pragma unroll
    for (int j = 0; j < 9; j++) {
        float a0, a1;
        upk(acc[j], a0, a1);
        atomicAdd(&out[(size_t)mbase*9 + j],     a0);
        atomicAdd(&out[(size_t)(mbase+1)*9 + j], a1);
    }
}

// ---------------- launch ------------------------------------------------------
extern "C" void kernel_launch(void* const* d_in, const int* in_sizes, int n_in,
                              void* d_out, int out_size) {
    const int*   x      = (const int*)  d_in[0];
    const float* conv_w = (const float*)d_in[1];
    const float* conv_b = (const float*)d_in[2];
    const float* bn0_g  = (const float*)d_in[3];
    const float* bn0_b  = (const float*)d_in[4];
    const float* w_rank = (const float*)d_in[5];
    const float* b_rank = (const float*)d_in[6];
    const float* w_h1   = (const float*)d_in[7];
    const float* b_h1   = (const float*)d_in[8];
    const float* bn1_g  = (const float*)d_in[9];
    const float* bn1_b  = (const float*)d_in[10];
    const float* w_h2   = (const float*)d_in[11];
    const float* b_h2   = (const float*)d_in[12];
    const float* bn2_g  = (const float*)d_in[13];
    const float* bn2_b  = (const float*)d_in[14];
    const float* w_out  = (const float*)d_in[15];
    const float* b_out  = (const float*)d_in[16];
    float* out = (float*)d_out;

    // Stage small weights into constant memory (async D2D copies, capturable).
    cudaMemcpyToSymbolAsync(c_wr,  w_rank, 320*4,  0, cudaMemcpyDeviceToDevice, 0);
    cudaMemcpyToSymbolAsync(c_br,  b_rank, 32*4,   0, cudaMemcpyDeviceToDevice, 0);
    cudaMemcpyToSymbolAsync(c_wh1, w_h1,   1024*4, 0, cudaMemcpyDeviceToDevice, 0);
    cudaMemcpyToSymbolAsync(c_bh1, b_h1,   32*4,   0, cudaMemcpyDeviceToDevice, 0);
    cudaMemcpyToSymbolAsync(c_wh2, w_h2,   512*4,  0, cudaMemcpyDeviceToDevice, 0);
    cudaMemcpyToSymbolAsync(c_bh2, b_h2,   16*4,   0, cudaMemcpyDeviceToDevice, 0);

    ktable<<<80, 1024>>>(conv_w);
    k1<<<dim3(16, 64), 256>>>(x);
    k2<<<1, 1024>>>(conv_b, bn0_g, bn0_b);
    k3<<<dim3(32, 64), 256>>>(x, conv_b);
    k4<<<1, 1024>>>(bn1_g, bn1_b);
    k5<<<dim3(32, 64), 256>>>();
    k6<<<1, 288>>>(bn2_g, bn2_b, w_out, b_out);
    k6b<<<144, 256>>>(out);
    k7<<<dim3(8, 32), 256>>>(w_out, out);
}

// round 6
// speedup vs baseline: 1.1282x; 1.1282x over previous
#include <cuda_runtime.h>
#include <cuda_fp16.h>
#include <math.h>

#define M 4096
#define CN 64
#define BNEPS 1e-5

typedef unsigned long long u64;

// ---------------- packed f32x2 helpers ----------------------------------------
__device__ __forceinline__ u64 pk(float lo, float hi) {
    u64 r; asm("mov.b64 %0,{%1,%2};" : "=l"(r) : "f"(lo), "f"(hi)); return r;
}
__device__ __forceinline__ void upk(u64 v, float& lo, float& hi) {
    asm("mov.b64 {%0,%1},%2;" : "=f"(lo), "=f"(hi) : "l"(v));
}
__device__ __forceinline__ u64 ffma2(u64 a, u64 b, u64 c) {
    u64 d; asm("fma.rn.f32x2 %0,%1,%2,%3;" : "=l"(d) : "l"(a), "l"(b), "l"(c)); return d;
}

// ---------------- constant-memory weights, single blob -------------------------
// layout: [0:320) w_rank | [320:352) b_rank | [352:1376) w_h1 | [1376:1408) b_h1
//         [1408:1920) w_h2 | [1920:1936) b_h2
__constant__ __align__(16) float c_all[1936];
#define c_wr  (c_all)
#define c_br  (c_all + 320)
#define c_wh1 (c_all + 352)
#define c_bh1 (c_all + 1376)
#define c_wh2 (c_all + 1408)
#define c_bh2 (c_all + 1920)

__device__ float g_stage[1936];

// ---------------- scratch (device globals; no allocs allowed) ----------------
__device__ float g_table[5*16*64*16];                 // 320 KB
__device__ float g_bn0s1[CN], g_bn0s2[CN];
__device__ float g_bn1s[CN],  g_bn1q[CN];
__device__ float g_bn2s[CN],  g_bn2q[CN];
__device__ float g_scale0[CN], g_shift0[CN], g_u0[CN];
__device__ float g_base_r[CN*32];
__device__ float g_rc3[CN*32];
__device__ float g_scale1[CN], g_shift1[CN];
__device__ float g_rc4[CN*16];
__device__ float g_scale2[CN], g_shift2[CN];
__device__ float g_outconst[16];
__device__ __half2 g_r3h[(size_t)CN*4*16*M];          // 64 MB, [c][h][o2][m], half2=(o even,o odd)
__device__ float g_r4[(size_t)CN*4*16*M];             // 64 MB, [c][h][o][m]

// ---------------- kpack: gather all small weights into one staging blob -------
__global__ void kpack(const float* __restrict__ wr, const float* __restrict__ br,
                      const float* __restrict__ wh1, const float* __restrict__ bh1,
                      const float* __restrict__ wh2, const float* __restrict__ bh2) {
    int t = blockIdx.x*1024 + threadIdx.x;
    if (t >= 1936) return;
    float v;
    if      (t < 320)  v = wr[t];
    else if (t < 352)  v = br[t - 320];
    else if (t < 1376) v = wh1[t - 352];
    else if (t < 1408) v = bh1[t - 1376];
    else if (t < 1920) v = wh2[t - 1408];
    else               v = bh2[t - 1920];
    g_stage[t] = v;
}

// ---------------- ktable: sparse-conv lookup table (+ accumulator zeroing) ----
__global__ void ktable(const float* __restrict__ conv_w) {
    int idx = blockIdx.x*blockDim.x + threadIdx.x;
    if (blockIdx.x == 0 && threadIdx.x < CN) {
        int t = threadIdx.x;
        g_bn0s1[t]=0.f; g_bn0s2[t]=0.f;
        g_bn1s[t]=0.f;  g_bn1q[t]=0.f;
        g_bn2s[t]=0.f;  g_bn2q[t]=0.f;
    }
    if (idx >= 5*16*64*16) return;
    int hw = idx & 15, c = (idx>>4)&63, combo = (idx>>10)&15, i = idx>>14;
    int h = hw>>2, w = hw&3, r = combo>>2, s = combo&3;
    float v = 0.f;
    if (h <= r && w <= s) v = conv_w[c*125 + i*25 + (r-h)*5 + (s-w)];
    g_table[idx] = v;
}

// Per-block shared slice of the table for channel c: stab[i*256 + combo*16 + k]
__device__ __forceinline__ void load_stab(float* stab, int c, int t, int nt) {
    for (int idx = t; idx < 1280; idx += nt) {
        int i = idx >> 8, rem = idx & 255;
        stab[idx] = g_table[(i*16 + (rem>>4))*1024 + c*16 + (rem&15)];
    }
}

__device__ __forceinline__ void compute_a_s(int m, const int* __restrict__ x,
                                            const float* __restrict__ stab, float* a) {
#pragma unroll
    for (int k = 0; k < 16; k++) a[k] = 0.f;
#pragma unroll
    for (int i = 0; i < 5; i++) {
        int r = x[m*10 + 2*i]     & 3;
        int s = x[m*10 + 2*i + 1] & 3;
        const float4* tp = reinterpret_cast<const float4*>(stab + i*256 + (r*4+s)*16);
        float4 t0 = tp[0], t1 = tp[1], t2 = tp[2], t3 = tp[3];
        a[0]+=t0.x; a[1]+=t0.y; a[2]+=t0.z; a[3]+=t0.w;
        a[4]+=t1.x; a[5]+=t1.y; a[6]+=t1.z; a[7]+=t1.w;
        a[8]+=t2.x; a[9]+=t2.y; a[10]+=t2.z; a[11]+=t2.w;
        a[12]+=t3.x; a[13]+=t3.y; a[14]+=t3.z; a[15]+=t3.w;
    }
}

// ---------------- k1: BN0 raw sums over the varying 4x4 region ----------------
__global__ void __launch_bounds__(256) k1(const int* __restrict__ x) {
    __shared__ __align__(16) float stab[1280];
    __shared__ float red_s, red_q;
    int c  = blockIdx.y;
    int t  = threadIdx.x;
    load_stab(stab, c, t, 256);
    if (t == 0) { red_s = 0.f; red_q = 0.f; }
    __syncthreads();
    int m = blockIdx.x*256 + t;
    float a[16];
    compute_a_s(m, x, stab, a);
    float s = 0.f, q = 0.f;
#pragma unroll
    for (int k = 0; k < 16; k++) { s += a[k]; q += a[k]*a[k]; }
    for (int off = 16; off; off >>= 1) {
        s += __shfl_down_sync(0xffffffffu, s, off);
        q += __shfl_down_sync(0xffffffffu, q, off);
    }
    if ((t & 31) == 0) { atomicAdd(&red_s, s); atomicAdd(&red_q, q); }
    __syncthreads();
    if (t == 0) {
        atomicAdd(&g_bn0s1[c], red_s);
        atomicAdd(&g_bn0s2[c], red_q);
    }
}

// ---------------- k2: finalize BN0, const path through w_rank/w_h1 -----------
__global__ void __launch_bounds__(1024) k2(const float* __restrict__ conv_b,
                   const float* __restrict__ bn0_g, const float* __restrict__ bn0_b) {
    __shared__ float shW4[32], shWall[32], su0[64];
    __shared__ float sh_rc2[2048];
    int t = threadIdx.x;
    if (t < 64) {
        double n0   = (double)M * 110.0;
        double mu_a = (double)g_bn0s1[t] / n0;
        double var  = (double)g_bn0s2[t] / n0 - mu_a*mu_a;
        double cb   = (double)conv_b[t];
        double mean = cb + mu_a;
        double sc   = (double)bn0_g[t] / sqrt(var + BNEPS);
        double sh   = (double)bn0_b[t] - mean*sc;
        g_scale0[t] = (float)sc;
        g_shift0[t] = (float)sh;
        float u0    = fmaxf((float)(cb*sc + sh), 0.f);
        g_u0[t]     = u0;
        su0[t]      = u0;
    }
    if (t < 32) {
        float w4 = 0.f, wall = 0.f;
        for (int w = 0; w < 10; w++) { float v = c_wr[t*10+w]; wall += v; if (w >= 4) w4 += v; }
        shW4[t] = w4; shWall[t] = wall;
    }
    __syncthreads();
#pragma unroll
    for (int rep = 0; rep < 2; rep++) {
        int idx = t + rep*1024;
        int c = idx >> 5, o = idx & 31;
        float br = c_br[o];
        g_base_r[idx] = su0[c]*shW4[o] + br;
        sh_rc2[idx]   = fmaxf(su0[c]*shWall[o] + br, 0.f);
    }
    __syncthreads();
#pragma unroll
    for (int rep = 0; rep < 2; rep++) {
        int idx = t + rep*1024;
        int c = idx >> 5, o = idx & 31;
        float acc = c_bh1[o];
#pragma unroll
        for (int i = 0; i < 32; i++) acc += sh_rc2[c*32+i] * c_wh1[o*32+i];
        g_rc3[idx] = acc;
        float s = acc, q = acc*acc;
        for (int off = 16; off; off >>= 1) {
            s += __shfl_down_sync(0xffffffffu, s, off);
            q += __shfl_down_sync(0xffffffffu, q, off);
        }
        if (o == 0) {
            float k = (float)(M*7);
            g_bn1s[c] += k*s;
            g_bn1q[c] += k*q;
        }
    }
}

// ---------------- k3: fused bn0+relu -> w_rank+relu -> w_h1 -------------------
// Thread = (sample m, h-pair hp). Const-port weights; fp16x2 output (o-pairs).
__global__ void __launch_bounds__(256, 3) k3(const int* __restrict__ x,
                                             const float* __restrict__ conv_b) {
    __shared__ __align__(16) float stab[1280];
    __shared__ float sbase[32];
    __shared__ float red_s, red_q;
    int c = blockIdx.y, t = threadIdx.x;
    load_stab(stab, c, t, 256);
    if (t < 32) sbase[t] = g_base_r[c*32 + t];
    if (t == 0) { red_s = 0.f; red_q = 0.f; }
    __syncthreads();

    int hp = t >> 7;                       // h-pair: rows {2hp, 2hp+1}
    int m  = blockIdx.x*128 + (t & 127);
    float sc0 = g_scale0[c];
    float pc0 = conv_b[c]*sc0 + g_shift0[c];

    // conv rows 2hp, 2hp+1 only (8 values)
    float a8[8];
#pragma unroll
    for (int k = 0; k < 8; k++) a8[k] = 0.f;
    const int2* xp = reinterpret_cast<const int2*>(x + m*10);
#pragma unroll
    for (int i = 0; i < 5; i++) {
        int2 cd = xp[i];
        const float4* tp = reinterpret_cast<const float4*>(
            stab + i*256 + ((cd.x & 3)*4 + (cd.y & 3))*16 + hp*8);
        float4 t0 = tp[0], t1 = tp[1];
        a8[0]+=t0.x; a8[1]+=t0.y; a8[2]+=t0.z; a8[3]+=t0.w;
        a8[4]+=t1.x; a8[5]+=t1.y; a8[6]+=t1.z; a8[7]+=t1.w;
    }
#pragma unroll
    for (int k = 0; k < 8; k++) a8[k] = fmaxf(a8[k]*sc0 + pc0, 0.f);   // bn0 + relu

    // w_rank stage (scalar, const weights), output packed i-adjacent
    u64 r2p0[16], r2p1[16];
#pragma unroll
    for (int hh = 0; hh < 2; hh++) {
        float b0 = a8[hh*4+0], b1 = a8[hh*4+1], b2 = a8[hh*4+2], b3 = a8[hh*4+3];
#pragma unroll
        for (int oo = 0; oo < 16; oo++) {
            float e0 = sbase[2*oo],   e1 = sbase[2*oo+1];
            e0 += b0*c_wr[(2*oo)*10+0];   e1 += b0*c_wr[(2*oo+1)*10+0];
            e0 += b1*c_wr[(2*oo)*10+1];   e1 += b1*c_wr[(2*oo+1)*10+1];
            e0 += b2*c_wr[(2*oo)*10+2];   e1 += b2*c_wr[(2*oo+1)*10+2];
            e0 += b3*c_wr[(2*oo)*10+3];   e1 += b3*c_wr[(2*oo+1)*10+3];
            u64 r = pk(fmaxf(e0, 0.f), fmaxf(e1, 0.f));
            if (hh == 0) r2p0[oo] = r; else r2p1[oo] = r;
        }
    }

    // w_h1 stage: process output pairs (2o2, 2o2+1) for both h rows
    float s = 0.f, q = 0.f;
    size_t bh0 = (size_t)((c*4 + 2*hp)*16)*M + m;     // half2 row (c, h0, o2=0)
#pragma unroll 2
    for (int o2 = 0; o2 < 16; o2++) {
        int oe = 2*o2, od = 2*o2 + 1;
        u64 aE0 = pk(c_bh1[oe], 0.f), aE1 = aE0;
        u64 aO0 = pk(c_bh1[od], 0.f), aO1 = aO0;
        const ulonglong2* wpe = reinterpret_cast<const ulonglong2*>(&c_wh1[oe*32]);
        const ulonglong2* wpo = reinterpret_cast<const ulonglong2*>(&c_wh1[od*32]);
#pragma unroll
        for (int i = 0; i < 8; i++) {
            ulonglong2 we = wpe[i], wo = wpo[i];
            aE0 = ffma2(r2p0[2*i], we.x, aE0); aE0 = ffma2(r2p0[2*i+1], we.y, aE0);
            aE1 = ffma2(r2p1[2*i], we.x, aE1); aE1 = ffma2(r2p1[2*i+1], we.y, aE1);
            aO0 = ffma2(r2p0[2*i], wo.x, aO0); aO0 = ffma2(r2p0[2*i+1], wo.y, aO0);
            aO1 = ffma2(r2p1[2*i], wo.x, aO1); aO1 = ffma2(r2p1[2*i+1], wo.y, aO1);
        }
        float e0l,e0h,e1l,e1h,o0l,o0h,o1l,o1h;
        upk(aE0,e0l,e0h); upk(aE1,e1l,e1h); upk(aO0,o0l,o0h); upk(aO1,o1l,o1h);
        float vE0 = e0l+e0h, vE1 = e1l+e1h, vO0 = o0l+o0h, vO1 = o1l+o1h;
        s += vE0 + vE1 + vO0 + vO1;
        q += vE0*vE0 + vE1*vE1 + vO0*vO0 + vO1*vO1;
        g_r3h[bh0 + (size_t)o2*M]        = __floats2half2_rn(vE0, vO0);   // h0
        g_r3h[bh0 + (size_t)(16+o2)*M]   = __floats2half2_rn(vE1, vO1);   // h0+1
    }
    for (int off = 16; off; off >>= 1) {
        s += __shfl_down_sync(0xffffffffu, s, off);
        q += __shfl_down_sync(0xffffffffu, q, off);
    }
    if ((t & 31) == 0) { atomicAdd(&red_s, s); atomicAdd(&red_q, q); }
    __syncthreads();
    if (t == 0) { atomicAdd(&g_bn1s[c], red_s); atomicAdd(&g_bn1q[c], red_q); }
}

// ---------------- k4: finalize BN1, const path through w_h2 -------------------
__global__ void __launch_bounds__(1024) k4(const float* __restrict__ bn1_g,
                                           const float* __restrict__ bn1_b) {
    __shared__ float rc3bn[2048];
    __shared__ float ssc[64], ssh[64];
    int t = threadIdx.x;
    if (t < 64) {
        double n1   = (double)M * 11.0 * 32.0;
        double mean = (double)g_bn1s[t] / n1;
        double var  = (double)g_bn1q[t] / n1 - mean*mean;
        double sc   = (double)bn1_g[t] / sqrt(var + BNEPS);
        double sh   = (double)bn1_b[t] - mean*sc;
        g_scale1[t] = (float)sc;  ssc[t] = (float)sc;
        g_shift1[t] = (float)sh;  ssh[t] = (float)sh;
    }
    __syncthreads();
#pragma unroll
    for (int rep = 0; rep < 2; rep++) {
        int idx = t + rep*1024;
        int c = idx >> 5;
        rc3bn[idx] = fmaxf(g_rc3[idx]*ssc[c] + ssh[c], 0.f);
    }
    __syncthreads();
    {
        int c = t >> 4, o = t & 15;
        float acc = c_bh2[o];
#pragma unroll
        for (int i = 0; i < 32; i++) acc += rc3bn[c*32+i] * c_wh2[o*32+i];
        g_rc4[t] = acc;
        float s = acc, q = acc*acc;
        for (int off = 8; off; off >>= 1) {
            s += __shfl_down_sync(0xffffffffu, s, off, 16);
            q += __shfl_down_sync(0xffffffffu, q, off, 16);
        }
        if (o == 0) {
            float k = (float)(M*7);
            g_bn2s[c] += k*s;
            g_bn2q[c] += k*q;
        }
    }
}

// ---------------- k5: fused bn1+relu -> w_h2, BN2 sums ------------------------
// Thread = (sample m, h-pair). fp16x2 input (one 4B load per i-pair).
__global__ void __launch_bounds__(256, 3) k5() {
    __shared__ float red_s, red_q;
    int c = blockIdx.y, t = threadIdx.x;
    if (t == 0) { red_s = 0.f; red_q = 0.f; }
    __syncthreads();

    int hp = t >> 7;
    int m  = blockIdx.x*128 + (t & 127);
    float sc1 = g_scale1[c], sf1 = g_shift1[c];

    u64 yp0[16], yp1[16];
    size_t rb = (size_t)((c*4 + 2*hp)*16)*M + m;      // half2 rows
#pragma unroll
    for (int i2 = 0; i2 < 16; i2++) {
        float2 f = __half22float2(g_r3h[rb + (size_t)i2*M]);
        yp0[i2] = pk(fmaxf(f.x*sc1 + sf1, 0.f), fmaxf(f.y*sc1 + sf1, 0.f));
    }
#pragma unroll
    for (int i2 = 0; i2 < 16; i2++) {
        float2 f = __half22float2(g_r3h[rb + (size_t)(16 + i2)*M]);
        yp1[i2] = pk(fmaxf(f.x*sc1 + sf1, 0.f), fmaxf(f.y*sc1 + sf1, 0.f));
    }

    float s = 0.f, q = 0.f;
    size_t wbase = (size_t)((c*4 + 2*hp)*16)*M + m;
#pragma unroll 4
    for (int o = 0; o < 16; o++) {
        u64 acc0 = pk(c_bh2[o], 0.f), acc1 = acc0;
        const ulonglong2* wp = reinterpret_cast<const ulonglong2*>(&c_wh2[o*32]);
#pragma unroll
        for (int i = 0; i < 8; i++) {
            ulonglong2 w2 = wp[i];
            acc0 = ffma2(yp0[2*i],   w2.x, acc0);
            acc0 = ffma2(yp0[2*i+1], w2.y, acc0);
            acc1 = ffma2(yp1[2*i],   w2.x, acc1);
            acc1 = ffma2(yp1[2*i+1], w2.y, acc1);
        }
        float l0, h0, l1, h1;
        upk(acc0, l0, h0); upk(acc1, l1, h1);
        float v0 = l0 + h0, v1 = l1 + h1;
        s += v0 + v1;
        q += v0*v0 + v1*v1;
        g_r4[wbase + (size_t)o*M]        = v0;
        g_r4[wbase + (size_t)(o + 16)*M] = v1;
    }
    for (int off = 16; off; off >>= 1) {
        s += __shfl_down_sync(0xffffffffu, s, off);
        q += __shfl_down_sync(0xffffffffu, q, off);
    }
    if ((t & 31) == 0) { atomicAdd(&red_s, s); atomicAdd(&red_q, q); }
    __syncthreads();
    if (t == 0) { atomicAdd(&g_bn2s[c], red_s); atomicAdd(&g_bn2q[c], red_q); }
}

// ---------------- k6: finalize BN2, constant-row output contribution ----------
__global__ void k6(const float* __restrict__ bn2_g, const float* __restrict__ bn2_b,
                   const float* __restrict__ w_out, const float* __restrict__ b_out) {
    __shared__ float rc5[64*16];
    int t = threadIdx.x;                              // 288 = 9 warps
    if (t < 64) {
        double n2   = (double)M * 11.0 * 16.0;
        double mean = (double)g_bn2s[t] / n2;
        double var  = (double)g_bn2q[t] / n2 - mean*mean;
        double sc   = (double)bn2_g[t] / sqrt(var + BNEPS);
        double sh   = (double)bn2_b[t] - mean*sc;
        g_scale2[t] = (float)sc;
        g_shift2[t] = (float)sh;
    }
    __syncthreads();
    for (int idx = t; idx < 1024; idx += 288) {
        int c = idx >> 4;
        rc5[idx] = fmaxf(g_rc4[idx]*g_scale2[c] + g_shift2[c], 0.f);
    }
    __syncthreads();
    int j = t >> 5, lane = t & 31;
    if (j < 9) {
        float acc = 0.f;
        for (int p = lane; p < 1024; p += 32) {
            int c = p >> 4, o = p & 15;
            float ws = 0.f;
#pragma unroll
            for (int h = 4; h < 11; h++) ws += w_out[j*11264 + c*176 + h*16 + o];
            acc += rc5[p]*ws;
        }
        for (int off = 16; off; off >>= 1) acc += __shfl_down_sync(0xffffffffu, acc, off);
        if (!lane) g_outconst[j] = b_out[j] + acc;
    }
}

// ---------------- k6b: seed output with constant part -------------------------
__global__ void k6b(float* __restrict__ out) {
    int idx = blockIdx.x*256 + threadIdx.x;
    if (idx < M*9) out[idx] = g_outconst[idx % 9];
}

// ---------------- k7: varying-feature GEMM (bn2+relu fused, f32x2 packed) -----
__global__ void __launch_bounds__(256) k7(const float* __restrict__ w_out,
                                          float* __restrict__ out) {
    __shared__ u64 sw[9*64];                          // duplicated-packed, 4.5 KB
    int t = threadIdx.x;
    int warp = t >> 5, lane = t & 31;
    int mbase = blockIdx.x*512 + warp*64 + lane*2;
    int c0 = blockIdx.y*2;
    u64 acc[9];
#pragma unroll
    for (int j = 0; j < 9; j++) acc[j] = 0;
    for (int cc = 0; cc < 2; cc++) {
        int c = c0 + cc;
        __syncthreads();
        for (int idx = t; idx < 576; idx += 256) {
            int j = idx / 64, qq = idx % 64;
            float w = w_out[j*11264 + c*176 + qq];
            sw[idx] = pk(w, w);
        }
        __syncthreads();
        float sc = g_scale2[c], sf = g_shift2[c];
        u64 scp = pk(sc, sc), sfp = pk(sf, sf);
        for (int qq = 0; qq < 64; qq++) {
            u64 v = *reinterpret_cast<const u64*>(&g_r4[(size_t)(c*64+qq)*M + mbase]);
            u64 y = ffma2(v, scp, sfp);
            float y0, y1; upk(y, y0, y1);
            y = pk(fmaxf(y0, 0.f), fmaxf(y1, 0.f));
#pragma unroll
            for (int j = 0; j < 9; j++) acc[j] = ffma2(y, sw[j*64+qq], acc[j]);
        }
    }
#pragma unroll
    for (int j = 0; j < 9; j++) {
        float a0, a1;
        upk(acc[j], a0, a1);
        atomicAdd(&out[(size_t)mbase*9 + j],     a0);
        atomicAdd(&out[(size_t)(mbase+1)*9 + j], a1);
    }
}

// ---------------- launch ------------------------------------------------------
extern "C" void kernel_launch(void* const* d_in, const int* in_sizes, int n_in,
                              void* d_out, int out_size) {
    const int*   x      = (const int*)  d_in[0];
    const float* conv_w = (const float*)d_in[1];
    const float* conv_b = (const float*)d_in[2];
    const float* bn0_g  = (const float*)d_in[3];
    const float* bn0_b  = (const float*)d_in[4];
    const float* w_rank = (const float*)d_in[5];
    const float* b_rank = (const float*)d_in[6];
    const float* w_h1   = (const float*)d_in[7];
    const float* b_h1   = (const float*)d_in[8];
    const float* bn1_g  = (const float*)d_in[9];
    const float* bn1_b  = (const float*)d_in[10];
    const float* w_h2   = (const float*)d_in[11];
    const float* b_h2   = (const float*)d_in[12];
    const float* bn2_g  = (const float*)d_in[13];
    const float* bn2_b  = (const float*)d_in[14];
    const float* w_out  = (const float*)d_in[15];
    const float* b_out  = (const float*)d_in[16];
    float* out = (float*)d_out;

    // Stage all small weights with ONE pack kernel + ONE symbol memcpy.
    kpack<<<2, 1024>>>(w_rank, b_rank, w_h1, b_h1, w_h2, b_h2);
    void* stage_ptr = nullptr;
    cudaGetSymbolAddress(&stage_ptr, g_stage);
    cudaMemcpyToSymbolAsync(c_all, stage_ptr, 1936*sizeof(float), 0,
                            cudaMemcpyDeviceToDevice, 0);

    ktable<<<80, 1024>>>(conv_w);
    k1<<<dim3(16, 64), 256>>>(x);
    k2<<<1, 1024>>>(conv_b, bn0_g, bn0_b);
    k3<<<dim3(32, 64), 256>>>(x, conv_b);
    k4<<<1, 1024>>>(bn1_g, bn1_b);
    k5<<<dim3(32, 64), 256>>>();
    k6<<<1, 288>>>(bn2_g, bn2_b, w_out, b_out);
    k6b<<<144, 256>>>(out);
    k7<<<dim3(8, 32), 256>>>(w_out, out);
}

// round 7
// speedup vs baseline: 1.3488x; 1.1955x over previous
#include <cuda_runtime.h>
#include <cuda_fp16.h>
#include <math.h>

#define M 4096
#define CN 64
#define BNEPS 1e-5

typedef unsigned long long u64;

// ---------------- packed f32x2 helpers ----------------------------------------
__device__ __forceinline__ u64 pk(float lo, float hi) {
    u64 r; asm("mov.b64 %0,{%1,%2};" : "=l"(r) : "f"(lo), "f"(hi)); return r;
}
__device__ __forceinline__ void upk(u64 v, float& lo, float& hi) {
    asm("mov.b64 {%0,%1},%2;" : "=f"(lo), "=f"(hi) : "l"(v));
}
__device__ __forceinline__ u64 ffma2(u64 a, u64 b, u64 c) {
    u64 d; asm("fma.rn.f32x2 %0,%1,%2,%3;" : "=l"(d) : "l"(a), "l"(b), "l"(c)); return d;
}

// ---------------- constant-memory weights (k3/k5 only: warp-UNIFORM access) ---
// layout: [0:320) w_rank | [320:352) b_rank | [352:1376) w_h1 | [1376:1408) b_h1
//         [1408:1920) w_h2 | [1920:1936) b_h2
__constant__ __align__(16) float c_all[1936];
#define c_wr  (c_all)
#define c_br  (c_all + 320)
#define c_wh1 (c_all + 352)
#define c_bh1 (c_all + 1376)
#define c_wh2 (c_all + 1408)
#define c_bh2 (c_all + 1920)

__device__ float g_stage[1936];

// ---------------- scratch (device globals; no allocs allowed) ----------------
__device__ float g_table[5*16*64*16];                 // 320 KB
__device__ float g_bn0s1[CN], g_bn0s2[CN];
__device__ float g_bn1s[CN],  g_bn1q[CN];
__device__ float g_bn2s[CN],  g_bn2q[CN];
__device__ float g_scale0[CN], g_shift0[CN], g_u0[CN];
__device__ float g_base_r[CN*32];
__device__ float g_rc3[CN*32];
__device__ float g_scale1[CN], g_shift1[CN];
__device__ float g_rc4[CN*16];
__device__ float g_scale2[CN], g_shift2[CN];
__device__ float g_outconst[16];
__device__ __half2 g_r3h[(size_t)CN*4*16*M];          // 64 MB, [c][h][o2][m], half2=(o even,o odd)
__device__ float g_r4[(size_t)CN*4*16*M];             // 64 MB, [c][h][o][m]

// ---------------- kpack: gather all small weights into one staging blob -------
__global__ void kpack(const float* __restrict__ wr, const float* __restrict__ br,
                      const float* __restrict__ wh1, const float* __restrict__ bh1,
                      const float* __restrict__ wh2, const float* __restrict__ bh2) {
    int t = blockIdx.x*1024 + threadIdx.x;
    if (t >= 1936) return;
    float v;
    if      (t < 320)  v = wr[t];
    else if (t < 352)  v = br[t - 320];
    else if (t < 1376) v = wh1[t - 352];
    else if (t < 1408) v = bh1[t - 1376];
    else if (t < 1920) v = wh2[t - 1408];
    else               v = bh2[t - 1920];
    g_stage[t] = v;
}

// ---------------- ktable: sparse-conv lookup table (+ accumulator zeroing) ----
__global__ void ktable(const float* __restrict__ conv_w) {
    int idx = blockIdx.x*blockDim.x + threadIdx.x;
    if (blockIdx.x == 0 && threadIdx.x < CN) {
        int t = threadIdx.x;
        g_bn0s1[t]=0.f; g_bn0s2[t]=0.f;
        g_bn1s[t]=0.f;  g_bn1q[t]=0.f;
        g_bn2s[t]=0.f;  g_bn2q[t]=0.f;
    }
    if (idx >= 5*16*64*16) return;
    int hw = idx & 15, c = (idx>>4)&63, combo = (idx>>10)&15, i = idx>>14;
    int h = hw>>2, w = hw&3, r = combo>>2, s = combo&3;
    float v = 0.f;
    if (h <= r && w <= s) v = conv_w[c*125 + i*25 + (r-h)*5 + (s-w)];
    g_table[idx] = v;
}

// Per-block shared slice of the table for channel c: stab[i*256 + combo*16 + k]
__device__ __forceinline__ void load_stab(float* stab, int c, int t, int nt) {
    for (int idx = t; idx < 1280; idx += nt) {
        int i = idx >> 8, rem = idx & 255;
        stab[idx] = g_table[(i*16 + (rem>>4))*1024 + c*16 + (rem&15)];
    }
}

__device__ __forceinline__ void compute_a_s(int m, const int* __restrict__ x,
                                            const float* __restrict__ stab, float* a) {
#pragma unroll
    for (int k = 0; k < 16; k++) a[k] = 0.f;
#pragma unroll
    for (int i = 0; i < 5; i++) {
        int r = x[m*10 + 2*i]     & 3;
        int s = x[m*10 + 2*i + 1] & 3;
        const float4* tp = reinterpret_cast<const float4*>(stab + i*256 + (r*4+s)*16);
        float4 t0 = tp[0], t1 = tp[1], t2 = tp[2], t3 = tp[3];
        a[0]+=t0.x; a[1]+=t0.y; a[2]+=t0.z; a[3]+=t0.w;
        a[4]+=t1.x; a[5]+=t1.y; a[6]+=t1.z; a[7]+=t1.w;
        a[8]+=t2.x; a[9]+=t2.y; a[10]+=t2.z; a[11]+=t2.w;
        a[12]+=t3.x; a[13]+=t3.y; a[14]+=t3.z; a[15]+=t3.w;
    }
}

// ---------------- k1: BN0 raw sums over the varying 4x4 region ----------------
__global__ void __launch_bounds__(256) k1(const int* __restrict__ x) {
    __shared__ __align__(16) float stab[1280];
    __shared__ float red_s, red_q;
    int c  = blockIdx.y;
    int t  = threadIdx.x;
    load_stab(stab, c, t, 256);
    if (t == 0) { red_s = 0.f; red_q = 0.f; }
    __syncthreads();
    int m = blockIdx.x*256 + t;
    float a[16];
    compute_a_s(m, x, stab, a);
    float s = 0.f, q = 0.f;
#pragma unroll
    for (int k = 0; k < 16; k++) { s += a[k]; q += a[k]*a[k]; }
    for (int off = 16; off; off >>= 1) {
        s += __shfl_down_sync(0xffffffffu, s, off);
        q += __shfl_down_sync(0xffffffffu, q, off);
    }
    if ((t & 31) == 0) { atomicAdd(&red_s, s); atomicAdd(&red_q, q); }
    __syncthreads();
    if (t == 0) {
        atomicAdd(&g_bn0s1[c], red_s);
        atomicAdd(&g_bn0s2[c], red_q);
    }
}

// ---------------- k2: finalize BN0, const path through w_rank/w_h1 -----------
// Weights staged global->smem TRANSPOSED+padded: reads are conflict-free.
__global__ void __launch_bounds__(1024) k2(const float* __restrict__ conv_b,
                   const float* __restrict__ bn0_g, const float* __restrict__ bn0_b,
                   const float* __restrict__ w_rank, const float* __restrict__ b_rank,
                   const float* __restrict__ w_h1,  const float* __restrict__ b_h1) {
    __shared__ float swT[32*33];                      // w_h1 transposed [i][o], pad 33
    __shared__ float shW4[32], shWall[32], su0[64], sbr[32], sbh1[32];
    __shared__ float sh_rc2[2048];
    int t = threadIdx.x;
    {
        int o = t >> 5, i = t & 31;                   // w_h1[o][i]
        swT[i*33 + o] = w_h1[t];
    }
    if (t < 64) {
        double n0   = (double)M * 110.0;
        double mu_a = (double)g_bn0s1[t] / n0;
        double var  = (double)g_bn0s2[t] / n0 - mu_a*mu_a;
        double cb   = (double)conv_b[t];
        double mean = cb + mu_a;
        double sc   = (double)bn0_g[t] / sqrt(var + BNEPS);
        double sh   = (double)bn0_b[t] - mean*sc;
        g_scale0[t] = (float)sc;
        g_shift0[t] = (float)sh;
        float u0    = fmaxf((float)(cb*sc + sh), 0.f);
        g_u0[t]     = u0;
        su0[t]      = u0;
    }
    if (t < 32) {
        float w4 = 0.f, wall = 0.f;
        for (int w = 0; w < 10; w++) { float v = w_rank[t*10+w]; wall += v; if (w >= 4) w4 += v; }
        shW4[t] = w4; shWall[t] = wall;
        sbr[t]  = b_rank[t];
        sbh1[t] = b_h1[t];
    }
    __syncthreads();
#pragma unroll
    for (int rep = 0; rep < 2; rep++) {
        int idx = t + rep*1024;
        int c = idx >> 5, o = idx & 31;
        float br = sbr[o];
        g_base_r[idx] = su0[c]*shW4[o] + br;
        sh_rc2[idx]   = fmaxf(su0[c]*shWall[o] + br, 0.f);
    }
    __syncthreads();
#pragma unroll
    for (int rep = 0; rep < 2; rep++) {
        int idx = t + rep*1024;
        int c = idx >> 5, o = idx & 31;               // c warp-uniform, o = lane
        float acc = sbh1[o];
#pragma unroll
        for (int i = 0; i < 32; i++) acc += sh_rc2[c*32+i] * swT[i*33+o];
        g_rc3[idx] = acc;
        float s = acc, q = acc*acc;
        for (int off = 16; off; off >>= 1) {
            s += __shfl_down_sync(0xffffffffu, s, off);
            q += __shfl_down_sync(0xffffffffu, q, off);
        }
        if (o == 0) {
            float k = (float)(M*7);
            g_bn1s[c] += k*s;
            g_bn1q[c] += k*q;
        }
    }
}

// ---------------- k3: fused bn0+relu -> w_rank+relu -> w_h1 -------------------
// Thread = (sample m, h-pair hp). Const-port weights (uniform); fp16x2 output.
__global__ void __launch_bounds__(256, 3) k3(const int* __restrict__ x,
                                             const float* __restrict__ conv_b) {
    __shared__ __align__(16) float stab[1280];
    __shared__ float sbase[32];
    __shared__ float red_s, red_q;
    int c = blockIdx.y, t = threadIdx.x;
    load_stab(stab, c, t, 256);
    if (t < 32) sbase[t] = g_base_r[c*32 + t];
    if (t == 0) { red_s = 0.f; red_q = 0.f; }
    __syncthreads();

    int hp = t >> 7;                       // h-pair: rows {2hp, 2hp+1}
    int m  = blockIdx.x*128 + (t & 127);
    float sc0 = g_scale0[c];
    float pc0 = conv_b[c]*sc0 + g_shift0[c];

    // conv rows 2hp, 2hp+1 only (8 values)
    float a8[8];
#pragma unroll
    for (int k = 0; k < 8; k++) a8[k] = 0.f;
    const int2* xp = reinterpret_cast<const int2*>(x + m*10);
#pragma unroll
    for (int i = 0; i < 5; i++) {
        int2 cd = xp[i];
        const float4* tp = reinterpret_cast<const float4*>(
            stab + i*256 + ((cd.x & 3)*4 + (cd.y & 3))*16 + hp*8);
        float4 t0 = tp[0], t1 = tp[1];
        a8[0]+=t0.x; a8[1]+=t0.y; a8[2]+=t0.z; a8[3]+=t0.w;
        a8[4]+=t1.x; a8[5]+=t1.y; a8[6]+=t1.z; a8[7]+=t1.w;
    }
#pragma unroll
    for (int k = 0; k < 8; k++) a8[k] = fmaxf(a8[k]*sc0 + pc0, 0.f);   // bn0 + relu

    // w_rank stage (scalar, const weights, uniform indices)
    u64 r2p0[16], r2p1[16];
#pragma unroll
    for (int hh = 0; hh < 2; hh++) {
        float b0 = a8[hh*4+0], b1 = a8[hh*4+1], b2 = a8[hh*4+2], b3 = a8[hh*4+3];
#pragma unroll
        for (int oo = 0; oo < 16; oo++) {
            float e0 = sbase[2*oo],   e1 = sbase[2*oo+1];
            e0 += b0*c_wr[(2*oo)*10+0];   e1 += b0*c_wr[(2*oo+1)*10+0];
            e0 += b1*c_wr[(2*oo)*10+1];   e1 += b1*c_wr[(2*oo+1)*10+1];
            e0 += b2*c_wr[(2*oo)*10+2];   e1 += b2*c_wr[(2*oo+1)*10+2];
            e0 += b3*c_wr[(2*oo)*10+3];   e1 += b3*c_wr[(2*oo+1)*10+3];
            u64 r = pk(fmaxf(e0, 0.f), fmaxf(e1, 0.f));
            if (hh == 0) r2p0[oo] = r; else r2p1[oo] = r;
        }
    }

    // w_h1 stage: process output pairs (2o2, 2o2+1) for both h rows
    float s = 0.f, q = 0.f;
    size_t bh0 = (size_t)((c*4 + 2*hp)*16)*M + m;     // half2 row (c, h0, o2=0)
#pragma unroll 2
    for (int o2 = 0; o2 < 16; o2++) {
        int oe = 2*o2, od = 2*o2 + 1;
        u64 aE0 = pk(c_bh1[oe], 0.f), aE1 = aE0;
        u64 aO0 = pk(c_bh1[od], 0.f), aO1 = aO0;
        const ulonglong2* wpe = reinterpret_cast<const ulonglong2*>(&c_wh1[oe*32]);
        const ulonglong2* wpo = reinterpret_cast<const ulonglong2*>(&c_wh1[od*32]);
#pragma unroll
        for (int i = 0; i < 8; i++) {
            ulonglong2 we = wpe[i], wo = wpo[i];
            aE0 = ffma2(r2p0[2*i], we.x, aE0); aE0 = ffma2(r2p0[2*i+1], we.y, aE0);
            aE1 = ffma2(r2p1[2*i], we.x, aE1); aE1 = ffma2(r2p1[2*i+1], we.y, aE1);
            aO0 = ffma2(r2p0[2*i], wo.x, aO0); aO0 = ffma2(r2p0[2*i+1], wo.y, aO0);
            aO1 = ffma2(r2p1[2*i], wo.x, aO1); aO1 = ffma2(r2p1[2*i+1], wo.y, aO1);
        }
        float e0l,e0h,e1l,e1h,o0l,o0h,o1l,o1h;
        upk(aE0,e0l,e0h); upk(aE1,e1l,e1h); upk(aO0,o0l,o0h); upk(aO1,o1l,o1h);
        float vE0 = e0l+e0h, vE1 = e1l+e1h, vO0 = o0l+o0h, vO1 = o1l+o1h;
        s += vE0 + vE1 + vO0 + vO1;
        q += vE0*vE0 + vE1*vE1 + vO0*vO0 + vO1*vO1;
        g_r3h[bh0 + (size_t)o2*M]        = __floats2half2_rn(vE0, vO0);   // h0
        g_r3h[bh0 + (size_t)(16+o2)*M]   = __floats2half2_rn(vE1, vO1);   // h0+1
    }
    for (int off = 16; off; off >>= 1) {
        s += __shfl_down_sync(0xffffffffu, s, off);
        q += __shfl_down_sync(0xffffffffu, q, off);
    }
    if ((t & 31) == 0) { atomicAdd(&red_s, s); atomicAdd(&red_q, q); }
    __syncthreads();
    if (t == 0) { atomicAdd(&g_bn1s[c], red_s); atomicAdd(&g_bn1q[c], red_q); }
}

// ---------------- k4: finalize BN1, const path through w_h2 -------------------
// w_h2 staged global->smem transposed+padded.
__global__ void __launch_bounds__(1024) k4(const float* __restrict__ bn1_g,
                                           const float* __restrict__ bn1_b,
                                           const float* __restrict__ w_h2,
                                           const float* __restrict__ b_h2) {
    __shared__ float rc3bn[2048];
    __shared__ float swT2[32*17];                     // w_h2 transposed [i][o], pad 17
    __shared__ float ssc[64], ssh[64], sbh2[16];
    int t = threadIdx.x;
    if (t < 512) {
        int o = t >> 5, i = t & 31;                   // w_h2[o][i]
        swT2[i*17 + o] = w_h2[t];
    }
    if (t < 64) {
        double n1   = (double)M * 11.0 * 32.0;
        double mean = (double)g_bn1s[t] / n1;
        double var  = (double)g_bn1q[t] / n1 - mean*mean;
        double sc   = (double)bn1_g[t] / sqrt(var + BNEPS);
        double sh   = (double)bn1_b[t] - mean*sc;
        g_scale1[t] = (float)sc;  ssc[t] = (float)sc;
        g_shift1[t] = (float)sh;  ssh[t] = (float)sh;
    }
    if (t < 16) sbh2[t] = b_h2[t];
    __syncthreads();
#pragma unroll
    for (int rep = 0; rep < 2; rep++) {
        int idx = t + rep*1024;
        int c = idx >> 5;
        rc3bn[idx] = fmaxf(g_rc3[idx]*ssc[c] + ssh[c], 0.f);
    }
    __syncthreads();
    {
        int c = t >> 4, o = t & 15;
        float acc = sbh2[o];
#pragma unroll
        for (int i = 0; i < 32; i++) acc += rc3bn[c*32+i] * swT2[i*17+o];
        g_rc4[t] = acc;
        float s = acc, q = acc*acc;
        for (int off = 8; off; off >>= 1) {
            s += __shfl_down_sync(0xffffffffu, s, off, 16);
            q += __shfl_down_sync(0xffffffffu, q, off, 16);
        }
        if (o == 0) {
            float k = (float)(M*7);
            g_bn2s[c] += k*s;
            g_bn2q[c] += k*q;
        }
    }
}

// ---------------- k5: fused bn1+relu -> w_h2, BN2 sums ------------------------
// Thread = (sample m, h-pair). fp16x2 input; const weights (uniform indices).
__global__ void __launch_bounds__(256, 3) k5() {
    __shared__ float red_s, red_q;
    int c = blockIdx.y, t = threadIdx.x;
    if (t == 0) { red_s = 0.f; red_q = 0.f; }
    __syncthreads();

    int hp = t >> 7;
    int m  = blockIdx.x*128 + (t & 127);
    float sc1 = g_scale1[c], sf1 = g_shift1[c];

    u64 yp0[16], yp1[16];
    size_t rb = (size_t)((c*4 + 2*hp)*16)*M + m;      // half2 rows
#pragma unroll
    for (int i2 = 0; i2 < 16; i2++) {
        float2 f = __half22float2(g_r3h[rb + (size_t)i2*M]);
        yp0[i2] = pk(fmaxf(f.x*sc1 + sf1, 0.f), fmaxf(f.y*sc1 + sf1, 0.f));
    }
#pragma unroll
    for (int i2 = 0; i2 < 16; i2++) {
        float2 f = __half22float2(g_r3h[rb + (size_t)(16 + i2)*M]);
        yp1[i2] = pk(fmaxf(f.x*sc1 + sf1, 0.f), fmaxf(f.y*sc1 + sf1, 0.f));
    }

    float s = 0.f, q = 0.f;
    size_t wbase = (size_t)((c*4 + 2*hp)*16)*M + m;
#pragma unroll 4
    for (int o = 0; o < 16; o++) {
        u64 acc0 = pk(c_bh2[o], 0.f), acc1 = acc0;
        const ulonglong2* wp = reinterpret_cast<const ulonglong2*>(&c_wh2[o*32]);
#pragma unroll
        for (int i = 0; i < 8; i++) {
            ulonglong2 w2 = wp[i];
            acc0 = ffma2(yp0[2*i],   w2.x, acc0);
            acc0 = ffma2(yp0[2*i+1], w2.y, acc0);
            acc1 = ffma2(yp1[2*i],   w2.x, acc1);
            acc1 = ffma2(yp1[2*i+1], w2.y, acc1);
        }
        float l0, h0, l1, h1;
        upk(acc0, l0, h0); upk(acc1, l1, h1);
        float v0 = l0 + h0, v1 = l1 + h1;
        s += v0 + v1;
        q += v0*v0 + v1*v1;
        g_r4[wbase + (size_t)o*M]        = v0;
        g_r4[wbase + (size_t)(o + 16)*M] = v1;
    }
    for (int off = 16; off; off >>= 1) {
        s += __shfl_down_sync(0xffffffffu, s, off);
        q += __shfl_down_sync(0xffffffffu, q, off);
    }
    if ((t & 31) == 0) { atomicAdd(&red_s, s); atomicAdd(&red_q, q); }
    __syncthreads();
    if (t == 0) { atomicAdd(&g_bn2s[c], red_s); atomicAdd(&g_bn2q[c], red_q); }
}

// ---------------- k6: finalize BN2, constant-row output contribution ----------
__global__ void k6(const float* __restrict__ bn2_g, const float* __restrict__ bn2_b,
                   const float* __restrict__ w_out, const float* __restrict__ b_out) {
    __shared__ float rc5[64*16];
    int t = threadIdx.x;                              // 288 = 9 warps
    if (t < 64) {
        double n2   = (double)M * 11.0 * 16.0;
        double mean = (double)g_bn2s[t] / n2;
        double var  = (double)g_bn2q[t] / n2 - mean*mean;
        double sc   = (double)bn2_g[t] / sqrt(var + BNEPS);
        double sh   = (double)bn2_b[t] - mean*sc;
        g_scale2[t] = (float)sc;
        g_shift2[t] = (float)sh;
    }
    __syncthreads();
    for (int idx = t; idx < 1024; idx += 288) {
        int c = idx >> 4;
        rc5[idx] = fmaxf(g_rc4[idx]*g_scale2[c] + g_shift2[c], 0.f);
    }
    __syncthreads();
    int j = t >> 5, lane = t & 31;
    if (j < 9) {
        float acc = 0.f;
        for (int p = lane; p < 1024; p += 32) {
            int c = p >> 4, o = p & 15;
            float ws = 0.f;
#pragma unroll
            for (int h = 4; h < 11; h++) ws += w_out[j*11264 + c*176 + h*16 + o];
            acc += rc5[p]*ws;
        }
        for (int off = 16; off; off >>= 1) acc += __shfl_down_sync(0xffffffffu, acc, off);
        if (!lane) g_outconst[j] = b_out[j] + acc;
    }
}

// ---------------- k6b: seed output with constant part -------------------------
__global__ void k6b(float* __restrict__ out) {
    int idx = blockIdx.x*256 + threadIdx.x;
    if (idx < M*9) out[idx] = g_outconst[idx % 9];
}

// ---------------- k7: varying-feature GEMM (bn2+relu fused, f32x2 packed) -----
__global__ void __launch_bounds__(256) k7(const float* __restrict__ w_out,
                                          float* __restrict__ out) {
    __shared__ u64 sw[9*64];                          // duplicated-packed, 4.5 KB
    int t = threadIdx.x;
    int warp = t >> 5, lane = t & 31;
    int mbase = blockIdx.x*512 + warp*64 + lane*2;
    int c0 = blockIdx.y*2;
    u64 acc[9];
#pragma unroll
    for (int j = 0; j < 9; j++) acc[j] = 0;
    for (int cc = 0; cc < 2; cc++) {
        int c = c0 + cc;
        __syncthreads();
        for (int idx = t; idx < 576; idx += 256) {
            int j = idx / 64, qq = idx % 64;
            float w = w_out[j*11264 + c*176 + qq];
            sw[idx] = pk(w, w);
        }
        __syncthreads();
        float sc = g_scale2[c], sf = g_shift2[c];
        u64 scp = pk(sc, sc), sfp = pk(sf, sf);
        for (int qq = 0; qq < 64; qq++) {
            u64 v = *reinterpret_cast<const u64*>(&g_r4[(size_t)(c*64+qq)*M + mbase]);
            u64 y = ffma2(v, scp, sfp);
            float y0, y1; upk(y, y0, y1);
            y = pk(fmaxf(y0, 0.f), fmaxf(y1, 0.f));
#pragma unroll
            for (int j = 0; j < 9; j++) acc[j] = ffma2(y, sw[j*64+qq], acc[j]);
        }
    }
#pragma unroll
    for (int j = 0; j < 9; j++) {
        float a0, a1;
        upk(acc[j], a0, a1);
        atomicAdd(&out[(size_t)mbase*9 + j],     a0);
        atomicAdd(&out[(size_t)(mbase+1)*9 + j], a1);
    }
}

// ---------------- launch ------------------------------------------------------
extern "C" void kernel_launch(void* const* d_in, const int* in_sizes, int n_in,
                              void* d_out, int out_size) {
    const int*   x      = (const int*)  d_in[0];
    const float* conv_w = (const float*)d_in[1];
    const float* conv_b = (const float*)d_in[2];
    const float* bn0_g  = (const float*)d_in[3];
    const float* bn0_b  = (const float*)d_in[4];
    const float* w_rank = (const float*)d_in[5];
    const float* b_rank = (const float*)d_in[6];
    const float* w_h1   = (const float*)d_in[7];
    const float* b_h1   = (const float*)d_in[8];
    const float* bn1_g  = (const float*)d_in[9];
    const float* bn1_b  = (const float*)d_in[10];
    const float* w_h2   = (const float*)d_in[11];
    const float* b_h2   = (const float*)d_in[12];
    const float* bn2_g  = (const float*)d_in[13];
    const float* bn2_b  = (const float*)d_in[14];
    const float* w_out  = (const float*)d_in[15];
    const float* b_out  = (const float*)d_in[16];
    float* out = (float*)d_out;

    // Stage all small weights with ONE pack kernel + ONE symbol memcpy.
    kpack<<<2, 1024>>>(w_rank, b_rank, w_h1, b_h1, w_h2, b_h2);
    void* stage_ptr = nullptr;
    cudaGetSymbolAddress(&stage_ptr, g_stage);
    cudaMemcpyToSymbolAsync(c_all, stage_ptr, 1936*sizeof(float), 0,
                            cudaMemcpyDeviceToDevice, 0);

    ktable<<<80, 1024>>>(conv_w);
    k1<<<dim3(16, 64), 256>>>(x);
    k2<<<1, 1024>>>(conv_b, bn0_g, bn0_b, w_rank, b_rank, w_h1, b_h1);
    k3<<<dim3(32, 64), 256>>>(x, conv_b);
    k4<<<1, 1024>>>(bn1_g, bn1_b, w_h2, b_h2);
    k5<<<dim3(32, 64), 256>>>();
    k6<<<1, 288>>>(bn2_g, bn2_b, w_out, b_out);
    k6b<<<144, 256>>>(out);
    k7<<<dim3(8, 32), 256>>>(w_out, out);
}

// round 8
// speedup vs baseline: 1.4980x; 1.1106x over previous
#include <cuda_runtime.h>
#include <cuda_fp16.h>
#include <math.h>

#define M 4096
#define CN 64
#define BNEPS 1e-5f

typedef unsigned long long u64;

// ---------------- packed f32x2 helpers ----------------------------------------
__device__ __forceinline__ u64 pk(float lo, float hi) {
    u64 r; asm("mov.b64 %0,{%1,%2};" : "=l"(r) : "f"(lo), "f"(hi)); return r;
}
__device__ __forceinline__ void upk(u64 v, float& lo, float& hi) {
    asm("mov.b64 {%0,%1},%2;" : "=f"(lo), "=f"(hi) : "l"(v));
}
__device__ __forceinline__ u64 ffma2(u64 a, u64 b, u64 c) {
    u64 d; asm("fma.rn.f32x2 %0,%1,%2,%3;" : "=l"(d) : "l"(a), "l"(b), "l"(c)); return d;
}

// ---------------- constant-memory weights (warp-UNIFORM access only) ----------
// [0:320) w_rank | [320:352) b_rank | [352:1376) w_h1 | [1376:1408) b_h1
// [1408:1920) w_h2 | [1920:1936) b_h2 | [1936:2064) w_rank pair-packed
__constant__ __align__(16) float c_all[2064];
#define c_wr   (c_all)
#define c_br   (c_all + 320)
#define c_wh1  (c_all + 352)
#define c_bh1  (c_all + 1376)
#define c_wh2  (c_all + 1408)
#define c_bh2  (c_all + 1920)
#define c_wrp  (c_all + 1936)   // [oo][w][2]: (wr[2oo][w], wr[2oo+1][w])

__device__ float g_stage[2064];

// ---------------- scratch (device globals; no allocs allowed) ----------------
__device__ float g_table[5*16*64*16];                 // 320 KB
__device__ int   g_cnt1[80];                          // [card i][combo]
__device__ int   g_cnt2[10*256];                      // [pair p][ci][cj]
__device__ float g_bn0s1[CN], g_bn0s2[CN];
__device__ float g_bn1s[CN],  g_bn1q[CN];
__device__ float g_bn2s[CN],  g_bn2q[CN];
__device__ float g_scale0[CN], g_shift0[CN], g_u0[CN];
__device__ float g_base_r[CN*32];
__device__ float g_rc3[CN*32];
__device__ float g_scale1[CN], g_shift1[CN];
__device__ float g_rc4[CN*16];
__device__ float g_scale2[CN], g_shift2[CN];
__device__ float g_outconst[16];
__device__ __half2 g_r3h[(size_t)CN*4*16*M];          // 64 MB, [c][h][o2][m]
__device__ __half2 g_r4h[(size_t)CN*32*M];            // 32 MB, [c][h*8+o2][m]

// ---------------- kpack: gather all small weights into one staging blob -------
__global__ void kpack(const float* __restrict__ wr, const float* __restrict__ br,
                      const float* __restrict__ wh1, const float* __restrict__ bh1,
                      const float* __restrict__ wh2, const float* __restrict__ bh2) {
    int t = blockIdx.x*1024 + threadIdx.x;
    if (t >= 2064) return;
    float v;
    if      (t < 320)  v = wr[t];
    else if (t < 352)  v = br[t - 320];
    else if (t < 1376) v = wh1[t - 352];
    else if (t < 1408) v = bh1[t - 1376];
    else if (t < 1920) v = wh2[t - 1408];
    else if (t < 1936) v = bh2[t - 1920];
    else {
        int idx = t - 1936;                           // pair-packed w_rank
        int oo = idx >> 3, w = (idx >> 1) & 3, half = idx & 1;
        v = wr[(2*oo + half)*10 + w];
    }
    g_stage[t] = v;
}

// ---------------- ktable: sparse-conv lookup table + accumulator zeroing ------
__global__ void ktable(const float* __restrict__ conv_w) {
    int idx = blockIdx.x*blockDim.x + threadIdx.x;
    if (blockIdx.x == 0) {
        int t = threadIdx.x;
        if (t < CN) { g_bn1s[t]=0.f; g_bn1q[t]=0.f; g_bn2s[t]=0.f; g_bn2q[t]=0.f; }
        for (int i = t; i < 80;   i += 1024) g_cnt1[i] = 0;
        for (int i = t; i < 2560; i += 1024) g_cnt2[i] = 0;
    }
    if (idx >= 5*16*64*16) return;
    int hw = idx & 15, c = (idx>>4)&63, combo = (idx>>10)&15, i = idx>>14;
    int h = hw>>2, w = hw&3, r = combo>>2, s = combo&3;
    float v = 0.f;
    if (h <= r && w <= s) v = conv_w[c*125 + i*25 + (r-h)*5 + (s-w)];
    g_table[idx] = v;
}

// ---------------- khist: combo histograms (single + pairwise) -----------------
__global__ void __launch_bounds__(256) khist(const int* __restrict__ x) {
    __shared__ int h1[80];
    __shared__ int h2[2560];
    int t = threadIdx.x;
    for (int i = t; i < 80;   i += 256) h1[i] = 0;
    for (int i = t; i < 2560; i += 256) h2[i] = 0;
    __syncthreads();
    int m = blockIdx.x*256 + t;
    int cb[5];
    const int2* xp = reinterpret_cast<const int2*>(x + m*10);
#pragma unroll
    for (int i = 0; i < 5; i++) {
        int2 cd = xp[i];
        cb[i] = (cd.x & 3)*4 + (cd.y & 3);
    }
#pragma unroll
    for (int i = 0; i < 5; i++) atomicAdd(&h1[i*16 + cb[i]], 1);
    int p = 0;
#pragma unroll
    for (int i = 0; i < 5; i++)
#pragma unroll
        for (int j = i+1; j < 5; j++) {
            atomicAdd(&h2[p*256 + cb[i]*16 + cb[j]], 1);
            p++;
        }
    __syncthreads();
    for (int i = t; i < 80;   i += 256) if (h1[i]) atomicAdd(&g_cnt1[i], h1[i]);
    for (int i = t; i < 2560; i += 256) if (h2[i]) atomicAdd(&g_cnt2[i], h2[i]);
}

// Per-block shared slice of the table for channel c: stab[i*256 + combo*16 + k]
__device__ __forceinline__ void load_stab(float* stab, int c, int t, int nt) {
    for (int idx = t; idx < 1280; idx += nt) {
        int i = idx >> 8, rem = idx & 255;
        stab[idx] = g_table[(i*16 + (rem>>4))*1024 + c*16 + (rem&15)];
    }
}

// ---------------- kbn0: BN0 raw sums from histograms (replaces k1) ------------
__global__ void __launch_bounds__(256) kbn0() {
    __shared__ __align__(16) float stab[1280];
    __shared__ float rs, rq;
    __shared__ int spi[10], spj[10];
    int c = blockIdx.x, t = threadIdx.x;
    load_stab(stab, c, t, 256);
    if (t == 0) {
        rs = 0.f; rq = 0.f;
        int p = 0;
        for (int i = 0; i < 5; i++)
            for (int j = i+1; j < 5; j++) { spi[p] = i; spj[p] = j; p++; }
    }
    __syncthreads();
    float s = 0.f, q = 0.f;
    for (int it = t; it < 80; it += 256) {            // diagonal terms
        int i = it >> 4, ci = it & 15;
        const float* b = &stab[i*256 + ci*16];
        float sd = 0.f, qd = 0.f;
#pragma unroll
        for (int k = 0; k < 16; k++) { float v = b[k]; sd += v; qd += v*v; }
        float cnt = (float)g_cnt1[it];
        s += cnt*sd;
        q += cnt*qd;
    }
    for (int it = t; it < 2560; it += 256) {          // cross terms
        int p = it >> 8, rem = it & 255, ci = rem >> 4, cj = rem & 15;
        int cnt = g_cnt2[it];
        if (cnt) {
            const float* a = &stab[spi[p]*256 + ci*16];
            const float* b = &stab[spj[p]*256 + cj*16];
            float d = 0.f;
#pragma unroll
            for (int k = 0; k < 16; k++) d += a[k]*b[k];
            q += 2.f*(float)cnt*d;
        }
    }
    for (int off = 16; off; off >>= 1) {
        s += __shfl_down_sync(0xffffffffu, s, off);
        q += __shfl_down_sync(0xffffffffu, q, off);
    }
    if ((t & 31) == 0) { atomicAdd(&rs, s); atomicAdd(&rq, q); }
    __syncthreads();
    if (t == 0) { g_bn0s1[c] = rs; g_bn0s2[c] = rq; }
}

// ---------------- k2: finalize BN0, const path through w_rank/w_h1 -----------
__global__ void __launch_bounds__(1024) k2(const float* __restrict__ conv_b,
                   const float* __restrict__ bn0_g, const float* __restrict__ bn0_b,
                   const float* __restrict__ w_rank, const float* __restrict__ b_rank,
                   const float* __restrict__ w_h1,  const float* __restrict__ b_h1) {
    __shared__ float swT[32*33];                      // w_h1 transposed [i][o], pad 33
    __shared__ float shW4[32], shWall[32], su0[64], sbr[32], sbh1[32];
    __shared__ float sh_rc2[2048];
    int t = threadIdx.x;
    {
        int o = t >> 5, i = t & 31;
        swT[i*33 + o] = w_h1[t];
    }
    if (t < 64) {
        float n0   = (float)M * 110.0f;
        float mu_a = g_bn0s1[t] / n0;
        float var  = g_bn0s2[t] / n0 - mu_a*mu_a;
        float cb   = conv_b[t];
        float mean = cb + mu_a;
        float sc   = bn0_g[t] * rsqrtf(var + BNEPS);
        float sh   = bn0_b[t] - mean*sc;
        g_scale0[t] = sc;
        g_shift0[t] = sh;
        float u0    = fmaxf(cb*sc + sh, 0.f);
        g_u0[t]     = u0;
        su0[t]      = u0;
    }
    if (t < 32) {
        float w4 = 0.f, wall = 0.f;
        for (int w = 0; w < 10; w++) { float v = w_rank[t*10+w]; wall += v; if (w >= 4) w4 += v; }
        shW4[t] = w4; shWall[t] = wall;
        sbr[t]  = b_rank[t];
        sbh1[t] = b_h1[t];
    }
    __syncthreads();
#pragma unroll
    for (int rep = 0; rep < 2; rep++) {
        int idx = t + rep*1024;
        int c = idx >> 5, o = idx & 31;
        float br = sbr[o];
        g_base_r[idx] = su0[c]*shW4[o] + br;
        sh_rc2[idx]   = fmaxf(su0[c]*shWall[o] + br, 0.f);
    }
    __syncthreads();
#pragma unroll
    for (int rep = 0; rep < 2; rep++) {
        int idx = t + rep*1024;
        int c = idx >> 5, o = idx & 31;
        float acc = sbh1[o];
#pragma unroll
        for (int i = 0; i < 32; i++) acc += sh_rc2[c*32+i] * swT[i*33+o];
        g_rc3[idx] = acc;
        float s = acc, q = acc*acc;
        for (int off = 16; off; off >>= 1) {
            s += __shfl_down_sync(0xffffffffu, s, off);
            q += __shfl_down_sync(0xffffffffu, q, off);
        }
        if (o == 0) {
            float k = (float)(M*7);
            g_bn1s[c] += k*s;
            g_bn1q[c] += k*q;
        }
    }
}

// ---------------- k3: fused bn0+relu -> w_rank+relu -> w_h1 -------------------
__global__ void __launch_bounds__(256, 3) k3(const int* __restrict__ x,
                                             const float* __restrict__ conv_b) {
    __shared__ __align__(16) float stab[1280];
    __shared__ u64 sbasep[16];
    __shared__ float red_s, red_q;
    int c = blockIdx.y, t = threadIdx.x;
    load_stab(stab, c, t, 256);
    if (t < 16) sbasep[t] = pk(g_base_r[c*32 + 2*t], g_base_r[c*32 + 2*t + 1]);
    if (t == 0) { red_s = 0.f; red_q = 0.f; }
    __syncthreads();

    int hp = t >> 7;                       // h-pair: rows {2hp, 2hp+1}
    int m  = blockIdx.x*128 + (t & 127);
    float sc0 = g_scale0[c];
    float pc0 = conv_b[c]*sc0 + g_shift0[c];

    float a8[8];
#pragma unroll
    for (int k = 0; k < 8; k++) a8[k] = 0.f;
    const int2* xp = reinterpret_cast<const int2*>(x + m*10);
#pragma unroll
    for (int i = 0; i < 5; i++) {
        int2 cd = xp[i];
        const float4* tp = reinterpret_cast<const float4*>(
            stab + i*256 + ((cd.x & 3)*4 + (cd.y & 3))*16 + hp*8);
        float4 t0 = tp[0], t1 = tp[1];
        a8[0]+=t0.x; a8[1]+=t0.y; a8[2]+=t0.z; a8[3]+=t0.w;
        a8[4]+=t1.x; a8[5]+=t1.y; a8[6]+=t1.z; a8[7]+=t1.w;
    }
#pragma unroll
    for (int k = 0; k < 8; k++) a8[k] = fmaxf(a8[k]*sc0 + pc0, 0.f);   // bn0 + relu

    // w_rank stage: pair-packed const weights (4 FFMA2 per output pair)
    u64 r2p0[16], r2p1[16];
#pragma unroll
    for (int hh = 0; hh < 2; hh++) {
        u64 b0p = pk(a8[hh*4+0], a8[hh*4+0]);
        u64 b1p = pk(a8[hh*4+1], a8[hh*4+1]);
        u64 b2p = pk(a8[hh*4+2], a8[hh*4+2]);
        u64 b3p = pk(a8[hh*4+3], a8[hh*4+3]);
#pragma unroll
        for (int oo = 0; oo < 16; oo++) {
            u64 e = sbasep[oo];
            const ulonglong2* wq = reinterpret_cast<const ulonglong2*>(&c_wrp[oo*8]);
            ulonglong2 wa = wq[0], wb = wq[1];
            e = ffma2(b0p, wa.x, e);
            e = ffma2(b1p, wa.y, e);
            e = ffma2(b2p, wb.x, e);
            e = ffma2(b3p, wb.y, e);
            float e0, e1; upk(e, e0, e1);
            u64 r = pk(fmaxf(e0, 0.f), fmaxf(e1, 0.f));
            if (hh == 0) r2p0[oo] = r; else r2p1[oo] = r;
        }
    }

    // w_h1 stage: output pairs (2o2, 2o2+1) for both h rows
    float s = 0.f, q = 0.f;
    size_t bh0 = (size_t)((c*4 + 2*hp)*16)*M + m;
#pragma unroll 2
    for (int o2 = 0; o2 < 16; o2++) {
        int oe = 2*o2, od = 2*o2 + 1;
        u64 aE0 = pk(c_bh1[oe], 0.f), aE1 = aE0;
        u64 aO0 = pk(c_bh1[od], 0.f), aO1 = aO0;
        const ulonglong2* wpe = reinterpret_cast<const ulonglong2*>(&c_wh1[oe*32]);
        const ulonglong2* wpo = reinterpret_cast<const ulonglong2*>(&c_wh1[od*32]);
#pragma unroll
        for (int i = 0; i < 8; i++) {
            ulonglong2 we = wpe[i], wo = wpo[i];
            aE0 = ffma2(r2p0[2*i], we.x, aE0); aE0 = ffma2(r2p0[2*i+1], we.y, aE0);
            aE1 = ffma2(r2p1[2*i], we.x, aE1); aE1 = ffma2(r2p1[2*i+1], we.y, aE1);
            aO0 = ffma2(r2p0[2*i], wo.x, aO0); aO0 = ffma2(r2p0[2*i+1], wo.y, aO0);
            aO1 = ffma2(r2p1[2*i], wo.x, aO1); aO1 = ffma2(r2p1[2*i+1], wo.y, aO1);
        }
        float e0l,e0h,e1l,e1h,o0l,o0h,o1l,o1h;
        upk(aE0,e0l,e0h); upk(aE1,e1l,e1h); upk(aO0,o0l,o0h); upk(aO1,o1l,o1h);
        float vE0 = e0l+e0h, vE1 = e1l+e1h, vO0 = o0l+o0h, vO1 = o1l+o1h;
        s += vE0 + vE1 + vO0 + vO1;
        q += vE0*vE0 + vE1*vE1 + vO0*vO0 + vO1*vO1;
        g_r3h[bh0 + (size_t)o2*M]        = __floats2half2_rn(vE0, vO0);   // h0
        g_r3h[bh0 + (size_t)(16+o2)*M]   = __floats2half2_rn(vE1, vO1);   // h0+1
    }
    for (int off = 16; off; off >>= 1) {
        s += __shfl_down_sync(0xffffffffu, s, off);
        q += __shfl_down_sync(0xffffffffu, q, off);
    }
    if ((t & 31) == 0) { atomicAdd(&red_s, s); atomicAdd(&red_q, q); }
    __syncthreads();
    if (t == 0) { atomicAdd(&g_bn1s[c], red_s); atomicAdd(&g_bn1q[c], red_q); }
}

// ---------------- k4: finalize BN1, const path through w_h2 -------------------
__global__ void __launch_bounds__(1024) k4(const float* __restrict__ bn1_g,
                                           const float* __restrict__ bn1_b,
                                           const float* __restrict__ w_h2,
                                           const float* __restrict__ b_h2) {
    __shared__ float rc3bn[2048];
    __shared__ float swT2[32*17];
    __shared__ float ssc[64], ssh[64], sbh2[16];
    int t = threadIdx.x;
    if (t < 512) {
        int o = t >> 5, i = t & 31;
        swT2[i*17 + o] = w_h2[t];
    }
    if (t < 64) {
        float n1   = (float)M * 11.0f * 32.0f;
        float mean = g_bn1s[t] / n1;
        float var  = g_bn1q[t] / n1 - mean*mean;
        float sc   = bn1_g[t] * rsqrtf(var + BNEPS);
        float sh   = bn1_b[t] - mean*sc;
        g_scale1[t] = sc;  ssc[t] = sc;
        g_shift1[t] = sh;  ssh[t] = sh;
    }
    if (t < 16) sbh2[t] = b_h2[t];
    __syncthreads();
#pragma unroll
    for (int rep = 0; rep < 2; rep++) {
        int idx = t + rep*1024;
        int c = idx >> 5;
        rc3bn[idx] = fmaxf(g_rc3[idx]*ssc[c] + ssh[c], 0.f);
    }
    __syncthreads();
    {
        int c = t >> 4, o = t & 15;
        float acc = sbh2[o];
#pragma unroll
        for (int i = 0; i < 32; i++) acc += rc3bn[c*32+i] * swT2[i*17+o];
        g_rc4[t] = acc;
        float s = acc, q = acc*acc;
        for (int off = 8; off; off >>= 1) {
            s += __shfl_down_sync(0xffffffffu, s, off, 16);
            q += __shfl_down_sync(0xffffffffu, q, off, 16);
        }
        if (o == 0) {
            float k = (float)(M*7);
            g_bn2s[c] += k*s;
            g_bn2q[c] += k*q;
        }
    }
}

// ---------------- k5: fused bn1+relu -> w_h2, BN2 sums (fp16 out, o-paired) ---
__global__ void __launch_bounds__(256, 3) k5() {
    __shared__ float red_s, red_q;
    int c = blockIdx.y, t = threadIdx.x;
    if (t == 0) { red_s = 0.f; red_q = 0.f; }
    __syncthreads();

    int hp = t >> 7;
    int m  = blockIdx.x*128 + (t & 127);
    float sc1 = g_scale1[c], sf1 = g_shift1[c];

    u64 yp0[16], yp1[16];
    size_t rb = (size_t)((c*4 + 2*hp)*16)*M + m;
#pragma unroll
    for (int i2 = 0; i2 < 16; i2++) {
        float2 f = __half22float2(g_r3h[rb + (size_t)i2*M]);
        yp0[i2] = pk(fmaxf(f.x*sc1 + sf1, 0.f), fmaxf(f.y*sc1 + sf1, 0.f));
    }
#pragma unroll
    for (int i2 = 0; i2 < 16; i2++) {
        float2 f = __half22float2(g_r3h[rb + (size_t)(16 + i2)*M]);
        yp1[i2] = pk(fmaxf(f.x*sc1 + sf1, 0.f), fmaxf(f.y*sc1 + sf1, 0.f));
    }

    float s = 0.f, q = 0.f;
    size_t wb = (size_t)(c*32)*M + m;                 // half2 rows: c*32 + h*8 + o2
#pragma unroll 2
    for (int o2 = 0; o2 < 8; o2++) {
        int oe = 2*o2, od = 2*o2 + 1;
        u64 aE0 = pk(c_bh2[oe], 0.f), aE1 = aE0;
        u64 aO0 = pk(c_bh2[od], 0.f), aO1 = aO0;
        const ulonglong2* wpe = reinterpret_cast<const ulonglong2*>(&c_wh2[oe*32]);
        const ulonglong2* wpo = reinterpret_cast<const ulonglong2*>(&c_wh2[od*32]);
#pragma unroll
        for (int i = 0; i < 8; i++) {
            ulonglong2 we = wpe[i], wo = wpo[i];
            aE0 = ffma2(yp0[2*i], we.x, aE0); aE0 = ffma2(yp0[2*i+1], we.y, aE0);
            aE1 = ffma2(yp1[2*i], we.x, aE1); aE1 = ffma2(yp1[2*i+1], we.y, aE1);
            aO0 = ffma2(yp0[2*i], wo.x, aO0); aO0 = ffma2(yp0[2*i+1], wo.y, aO0);
            aO1 = ffma2(yp1[2*i], wo.x, aO1); aO1 = ffma2(yp1[2*i+1], wo.y, aO1);
        }
        float e0l,e0h,e1l,e1h,o0l,o0h,o1l,o1h;
        upk(aE0,e0l,e0h); upk(aE1,e1l,e1h); upk(aO0,o0l,o0h); upk(aO1,o1l,o1h);
        float vE0 = e0l+e0h, vE1 = e1l+e1h, vO0 = o0l+o0h, vO1 = o1l+o1h;
        s += vE0 + vE1 + vO0 + vO1;
        q += vE0*vE0 + vE1*vE1 + vO0*vO0 + vO1*vO1;
        g_r4h[wb + (size_t)((2*hp)*8   + o2)*M] = __floats2half2_rn(vE0, vO0);
        g_r4h[wb + (size_t)((2*hp+1)*8 + o2)*M] = __floats2half2_rn(vE1, vO1);
    }
    for (int off = 16; off; off >>= 1) {
        s += __shfl_down_sync(0xffffffffu, s, off);
        q += __shfl_down_sync(0xffffffffu, q, off);
    }
    if ((t & 31) == 0) { atomicAdd(&red_s, s); atomicAdd(&red_q, q); }
    __syncthreads();
    if (t == 0) { atomicAdd(&g_bn2s[c], red_s); atomicAdd(&g_bn2q[c], red_q); }
}

// ---------------- k6: finalize BN2, constant-row output contribution ----------
__global__ void k6(const float* __restrict__ bn2_g, const float* __restrict__ bn2_b,
                   const float* __restrict__ w_out, const float* __restrict__ b_out) {
    __shared__ float rc5[64*16];
    int t = threadIdx.x;                              // 288 = 9 warps
    if (t < 64) {
        float n2   = (float)M * 11.0f * 16.0f;
        float mean = g_bn2s[t] / n2;
        float var  = g_bn2q[t] / n2 - mean*mean;
        float sc   = bn2_g[t] * rsqrtf(var + BNEPS);
        float sh   = bn2_b[t] - mean*sc;
        g_scale2[t] = sc;
        g_shift2[t] = sh;
    }
    __syncthreads();
    for (int idx = t; idx < 1024; idx += 288) {
        int c = idx >> 4;
        rc5[idx] = fmaxf(g_rc4[idx]*g_scale2[c] + g_shift2[c], 0.f);
    }
    __syncthreads();
    int j = t >> 5, lane = t & 31;
    if (j < 9) {
        float acc = 0.f;
        for (int p = lane; p < 1024; p += 32) {
            int c = p >> 4, o = p & 15;
            float ws = 0.f;
#pragma unroll
            for (int h = 4; h < 11; h++) ws += w_out[j*11264 + c*176 + h*16 + o];
            acc += rc5[p]*ws;
        }
        for (int off = 16; off; off >>= 1) acc += __shfl_down_sync(0xffffffffu, acc, off);
        if (!lane) g_outconst[j] = b_out[j] + acc;
    }
}

// ---------------- k6b: seed output with constant part -------------------------
__global__ void k6b(float* __restrict__ out) {
    int idx = blockIdx.x*256 + threadIdx.x;
    if (idx < M*9) out[idx] = g_outconst[idx % 9];
}

// ---------------- k7: varying-feature GEMM (bn2+relu fused, fp16 in) ----------
__global__ void __launch_bounds__(256) k7(const float* __restrict__ w_out,
                                          float* __restrict__ out) {
    __shared__ u64 swe[9*32], swo[9*32];              // dup-packed per feature pair
    int t = threadIdx.x;
    int warp = t >> 5, lane = t & 31;
    int mbase = blockIdx.x*1024 + warp*128 + lane*4;  // 4 samples/thread, gridDim.x=4
    int c0 = blockIdx.y*2;                            // gridDim.y=32
    u64 accA[9], accB[9];
#pragma unroll
    for (int j = 0; j < 9; j++) { accA[j] = 0; accB[j] = 0; }
    for (int cc = 0; cc < 2; cc++) {
        int c = c0 + cc;
        __syncthreads();
        for (int idx = t; idx < 576; idx += 256) {
            int j = idx / 64, r = idx % 64, qq2 = r >> 1, eo = r & 1;
            int h = qq2 >> 3, o2 = qq2 & 7;
            float w = w_out[j*11264 + c*176 + h*16 + 2*o2 + eo];
            (eo ? swo : swe)[j*32 + qq2] = pk(w, w);
        }
        __syncthreads();
        float sc = g_scale2[c], sf = g_shift2[c];
        for (int qq2 = 0; qq2 < 32; qq2++) {
            const __half2* row = &g_r4h[(size_t)(c*32 + qq2)*M];
            uint2 ua = *reinterpret_cast<const uint2*>(row + mbase);      // m, m+1
            uint2 ub = *reinterpret_cast<const uint2*>(row + mbase + 2);  // m+2, m+3
            float2 f0 = __half22float2(*reinterpret_cast<__half2*>(&ua.x));
            float2 f1 = __half22float2(*reinterpret_cast<__half2*>(&ua.y));
            float2 f2 = __half22float2(*reinterpret_cast<__half2*>(&ub.x));
            float2 f3 = __half22float2(*reinterpret_cast<__half2*>(&ub.y));
            u64 yeA = pk(fmaxf(f0.x*sc+sf, 0.f), fmaxf(f1.x*sc+sf, 0.f));
            u64 yoA = pk(fmaxf(f0.y*sc+sf, 0.f), fmaxf(f1.y*sc+sf, 0.f));
            u64 yeB = pk(fmaxf(f2.x*sc+sf, 0.f), fmaxf(f3.x*sc+sf, 0.f));
            u64 yoB = pk(fmaxf(f2.y*sc+sf, 0.f), fmaxf(f3.y*sc+sf, 0.f));
#pragma unroll
            for (int j = 0; j < 9; j++) {
                u64 we = swe[j*32 + qq2], wo = swo[j*32 + qq2];
                accA[j] = ffma2(yeA, we, accA[j]);
                accA[j] = ffma2(yoA, wo, accA[j]);
                accB[j] = ffma2(yeB, we, accB[j]);
                accB[j] = ffma2(yoB, wo, accB[j]);
            }
        }
    }
#pragma unroll
    for (int j = 0; j < 9; j++) {
        float a0, a1, b0, b1;
        upk(accA[j], a0, a1);
        upk(accB[j], b0, b1);
        atomicAdd(&out[(size_t)mbase*9 + j],     a0);
        atomicAdd(&out[(size_t)(mbase+1)*9 + j], a1);
        atomicAdd(&out[(size_t)(mbase+2)*9 + j], b0);
        atomicAdd(&out[(size_t)(mbase+3)*9 + j], b1);
    }
}

// ---------------- launch ------------------------------------------------------
extern "C" void kernel_launch(void* const* d_in, const int* in_sizes, int n_in,
                              void* d_out, int out_size) {
    const int*   x      = (const int*)  d_in[0];
    const float* conv_w = (const float*)d_in[1];
    const float* conv_b = (const float*)d_in[2];
    const float* bn0_g  = (const float*)d_in[3];
    const float* bn0_b  = (const float*)d_in[4];
    const float* w_rank = (const float*)d_in[5];
    const float* b_rank = (const float*)d_in[6];
    const float* w_h1   = (const float*)d_in[7];
    const float* b_h1   = (const float*)d_in[8];
    const float* bn1_g  = (const float*)d_in[9];
    const float* bn1_b  = (const float*)d_in[10];
    const float* w_h2   = (const float*)d_in[11];
    const float* b_h2   = (const float*)d_in[12];
    const float* bn2_g  = (const float*)d_in[13];
    const float* bn2_b  = (const float*)d_in[14];
    const float* w_out  = (const float*)d_in[15];
    const float* b_out  = (const float*)d_in[16];
    float* out = (float*)d_out;

    kpack<<<3, 1024>>>(w_rank, b_rank, w_h1, b_h1, w_h2, b_h2);
    void* stage_ptr = nullptr;
    cudaGetSymbolAddress(&stage_ptr, g_stage);
    cudaMemcpyToSymbolAsync(c_all, stage_ptr, 2064*sizeof(float), 0,
                            cudaMemcpyDeviceToDevice, 0);

    ktable<<<80, 1024>>>(conv_w);
    khist<<<16, 256>>>(x);
    kbn0<<<64, 256>>>();
    k2<<<1, 1024>>>(conv_b, bn0_g, bn0_b, w_rank, b_rank, w_h1, b_h1);
    k3<<<dim3(32, 64), 256>>>(x, conv_b);
    k4<<<1, 1024>>>(bn1_g, bn1_b, w_h2, b_h2);
    k5<<<dim3(32, 64), 256>>>();
    k6<<<1, 288>>>(bn2_g, bn2_b, w_out, b_out);
    k6b<<<144, 256>>>(out);
    k7<<<dim3(4, 32), 256>>>(w_out, out);
}

// round 9
// speedup vs baseline: 1.5037x; 1.0038x over previous
#include <cuda_runtime.h>
#include <cuda_fp16.h>
#include <math.h>

#define M 4096
#define CN 64
#define BNEPS 1e-5f

typedef unsigned long long u64;

// ---------------- packed f32x2 helpers ----------------------------------------
__device__ __forceinline__ u64 pk(float lo, float hi) {
    u64 r; asm("mov.b64 %0,{%1,%2};" : "=l"(r) : "f"(lo), "f"(hi)); return r;
}
__device__ __forceinline__ void upk(u64 v, float& lo, float& hi) {
    asm("mov.b64 {%0,%1},%2;" : "=f"(lo), "=f"(hi) : "l"(v));
}
__device__ __forceinline__ u64 ffma2(u64 a, u64 b, u64 c) {
    u64 d; asm("fma.rn.f32x2 %0,%1,%2,%3;" : "=l"(d) : "l"(a), "l"(b), "l"(c)); return d;
}

// ---------------- constant-memory weights (warp-UNIFORM access only) ----------
// [0:320) w_rank | [320:352) b_rank | [352:1376) w_h1 | [1376:1408) b_h1
// [1408:1920) w_h2 | [1920:1936) b_h2 | [1936:2064) w_rank pair-packed
__constant__ __align__(16) float c_all[2064];
#define c_wr   (c_all)
#define c_br   (c_all + 320)
#define c_wh1  (c_all + 352)
#define c_bh1  (c_all + 1376)
#define c_wh2  (c_all + 1408)
#define c_bh2  (c_all + 1920)
#define c_wrp  (c_all + 1936)   // [oo][w][2]: (wr[2oo][w], wr[2oo+1][w])

__device__ float g_stage[2064];

// ---------------- scratch (device globals; no allocs allowed) ----------------
__device__ float g_table[5*16*64*16];                 // 320 KB
__device__ int   g_cnt1[80];                          // [card i][combo]
__device__ int   g_cnt2[10*256];                      // [pair p][ci][cj]
__device__ float g_bn1s[CN],  g_bn1q[CN];
__device__ float g_bn2s[CN],  g_bn2q[CN];
__device__ float g_scale0[CN], g_shift0[CN];
__device__ float g_base_r[CN*32];
__device__ float g_rc3[CN*32];
__device__ float g_scale1[CN], g_shift1[CN];
__device__ float g_rc4[CN*16];
__device__ float g_scale2[CN], g_shift2[CN];
__device__ float g_outconst[16];
__device__ __half2 g_r3h[(size_t)CN*4*16*M];          // 64 MB, [c][h][o2][m]
__device__ __half2 g_r4h[(size_t)CN*32*M];            // 32 MB, [c][h*8+o2][m]

// ---------------- kpack: weights blob + histogram zeroing ---------------------
__global__ void kpack(const float* __restrict__ wr, const float* __restrict__ br,
                      const float* __restrict__ wh1, const float* __restrict__ bh1,
                      const float* __restrict__ wh2, const float* __restrict__ bh2) {
    int t = blockIdx.x*1024 + threadIdx.x;
    if (blockIdx.x == 0) {
        for (int i = threadIdx.x; i < 80;   i += 1024) g_cnt1[i] = 0;
        for (int i = threadIdx.x; i < 2560; i += 1024) g_cnt2[i] = 0;
    }
    if (t >= 2064) return;
    float v;
    if      (t < 320)  v = wr[t];
    else if (t < 352)  v = br[t - 320];
    else if (t < 1376) v = wh1[t - 352];
    else if (t < 1408) v = bh1[t - 1376];
    else if (t < 1920) v = wh2[t - 1408];
    else if (t < 1936) v = bh2[t - 1920];
    else {
        int idx = t - 1936;
        int oo = idx >> 3, w = (idx >> 1) & 3, half = idx & 1;
        v = wr[(2*oo + half)*10 + w];
    }
    g_stage[t] = v;
}

// ---------------- ktable: table build (blocks 0-79) + histograms (80-83) ------
__global__ void __launch_bounds__(1024) ktable(const float* __restrict__ conv_w,
                                               const int* __restrict__ x) {
    __shared__ int h1[80];
    __shared__ int h2[2560];
    int bx = blockIdx.x, t = threadIdx.x;
    if (bx < 80) {
        int idx = bx*1024 + t;
        int hw = idx & 15, c = (idx>>4)&63, combo = (idx>>10)&15, i = idx>>14;
        int h = hw>>2, w = hw&3, r = combo>>2, s = combo&3;
        float v = 0.f;
        if (h <= r && w <= s) v = conv_w[c*125 + i*25 + (r-h)*5 + (s-w)];
        g_table[idx] = v;
        return;
    }
    // histogram blocks: 4 blocks x 1024 threads = 4096 samples
    for (int i = t; i < 80;   i += 1024) h1[i] = 0;
    for (int i = t; i < 2560; i += 1024) h2[i] = 0;
    __syncthreads();
    int m = (bx - 80)*1024 + t;
    int cb[5];
    const int2* xp = reinterpret_cast<const int2*>(x + m*10);
#pragma unroll
    for (int i = 0; i < 5; i++) {
        int2 cd = xp[i];
        cb[i] = (cd.x & 3)*4 + (cd.y & 3);
    }
#pragma unroll
    for (int i = 0; i < 5; i++) atomicAdd(&h1[i*16 + cb[i]], 1);
    int p = 0;
#pragma unroll
    for (int i = 0; i < 5; i++)
#pragma unroll
        for (int j = i+1; j < 5; j++) {
            atomicAdd(&h2[p*256 + cb[i]*16 + cb[j]], 1);
            p++;
        }
    __syncthreads();
    for (int i = t; i < 80;   i += 1024) if (h1[i]) atomicAdd(&g_cnt1[i], h1[i]);
    for (int i = t; i < 2560; i += 1024) if (h2[i]) atomicAdd(&g_cnt2[i], h2[i]);
}

// Per-block shared slice of the table for channel c (k3 layout, stride 16)
__device__ __forceinline__ void load_stab(float* stab, int c, int t, int nt) {
    for (int idx = t; idx < 1280; idx += nt) {
        int i = idx >> 8, rem = idx & 255;
        stab[idx] = g_table[(i*16 + (rem>>4))*1024 + c*16 + (rem&15)];
    }
}

// ---------------- kbn0k2: BN0 stats from histograms + ALL of old k2 per-c -----
__global__ void __launch_bounds__(256) kbn0k2(const float* __restrict__ conv_b,
                   const float* __restrict__ bn0_g, const float* __restrict__ bn0_b,
                   const float* __restrict__ w_rank, const float* __restrict__ b_rank,
                   const float* __restrict__ w_h1,  const float* __restrict__ b_h1) {
    __shared__ float stab17[5*16*17];                 // padded: conflict-free
    __shared__ float swT[32*33];                      // w_h1 transposed [i][o]
    __shared__ float rc2[32];
    __shared__ float red_s, red_q, s_u0;
    __shared__ int spi[10], spj[10];
    int c = blockIdx.x, t = threadIdx.x;
    for (int idx = t; idx < 1280; idx += 256) {
        int i = idx >> 8, rem = idx & 255;
        stab17[(i*16 + (rem>>4))*17 + (rem&15)] =
            g_table[(i*16 + (rem>>4))*1024 + c*16 + (rem&15)];
    }
    for (int idx = t; idx < 1024; idx += 256) {
        int o = idx >> 5, i = idx & 31;
        swT[i*33 + o] = w_h1[idx];
    }
    if (t == 0) {
        red_s = 0.f; red_q = 0.f;
        int p = 0;
        for (int i = 0; i < 5; i++)
            for (int j = i+1; j < 5; j++) { spi[p] = i; spj[p] = j; p++; }
    }
    __syncthreads();
    float s = 0.f, q = 0.f;
    for (int it = t; it < 80; it += 256) {            // diagonal terms
        int i = it >> 4, ci = it & 15;
        const float* b = &stab17[(i*16 + ci)*17];
        float sd = 0.f, qd = 0.f;
#pragma unroll
        for (int k = 0; k < 16; k++) { float v = b[k]; sd += v; qd += v*v; }
        float cnt = (float)g_cnt1[it];
        s += cnt*sd;
        q += cnt*qd;
    }
    for (int it = t; it < 2560; it += 256) {          // cross terms
        int p = it >> 8, ci = (it >> 4) & 15, cj = it & 15;
        int cnt = g_cnt2[it];
        if (cnt) {
            const float* a = &stab17[(spi[p]*16 + ci)*17];
            const float* b = &stab17[(spj[p]*16 + cj)*17];
            float d = 0.f;
#pragma unroll
            for (int k = 0; k < 16; k++) d += a[k]*b[k];
            q += 2.f*(float)cnt*d;
        }
    }
    for (int off = 16; off; off >>= 1) {
        s += __shfl_down_sync(0xffffffffu, s, off);
        q += __shfl_down_sync(0xffffffffu, q, off);
    }
    if ((t & 31) == 0) { atomicAdd(&red_s, s); atomicAdd(&red_q, q); }
    __syncthreads();
    if (t == 0) {                                     // BN0 finalize for channel c
        float n0   = (float)M * 110.0f;
        float mu_a = red_s / n0;
        float var  = red_q / n0 - mu_a*mu_a;
        float cb   = conv_b[c];
        float sc   = bn0_g[c] * rsqrtf(var + BNEPS);
        float sh   = bn0_b[c] - (cb + mu_a)*sc;
        g_scale0[c] = sc;
        g_shift0[c] = sh;
        s_u0 = fmaxf(cb*sc + sh, 0.f);
    }
    __syncthreads();
    if (t < 32) {                                     // const path (old k2), this c only
        float u0 = s_u0;
        float w4 = 0.f, wall = 0.f;
        for (int w = 0; w < 10; w++) { float v = w_rank[t*10+w]; wall += v; if (w >= 4) w4 += v; }
        float br = b_rank[t];
        g_base_r[c*32 + t] = u0*w4 + br;
        rc2[t] = fmaxf(u0*wall + br, 0.f);
    }
    __syncthreads();
    if (t < 32) {
        float acc = b_h1[t];
#pragma unroll
        for (int i = 0; i < 32; i++) acc += rc2[i] * swT[i*33 + t];
        g_rc3[c*32 + t] = acc;
        float s2 = acc, q2 = acc*acc;
        for (int off = 16; off; off >>= 1) {
            s2 += __shfl_down_sync(0xffffffffu, s2, off);
            q2 += __shfl_down_sync(0xffffffffu, q2, off);
        }
        if (t == 0) {                                 // plain writes; k3 atomicAdds after
            g_bn1s[c] = (float)(M*7)*s2;
            g_bn1q[c] = (float)(M*7)*q2;
        }
    }
}

// ---------------- k3: fused bn0+relu -> w_rank+relu -> w_h1 -------------------
__global__ void __launch_bounds__(256, 3) k3(const int* __restrict__ x,
                                             const float* __restrict__ conv_b) {
    __shared__ __align__(16) float stab[1280];
    __shared__ u64 sbasep[16];
    __shared__ float red_s, red_q;
    int c = blockIdx.y, t = threadIdx.x;
    load_stab(stab, c, t, 256);
    if (t < 16) sbasep[t] = pk(g_base_r[c*32 + 2*t], g_base_r[c*32 + 2*t + 1]);
    if (t == 0) { red_s = 0.f; red_q = 0.f; }
    __syncthreads();

    int hp = t >> 7;                       // h-pair: rows {2hp, 2hp+1}
    int m  = blockIdx.x*128 + (t & 127);
    float sc0 = g_scale0[c];
    float pc0 = conv_b[c]*sc0 + g_shift0[c];

    float a8[8];
#pragma unroll
    for (int k = 0; k < 8; k++) a8[k] = 0.f;
    const int2* xp = reinterpret_cast<const int2*>(x + m*10);
#pragma unroll
    for (int i = 0; i < 5; i++) {
        int2 cd = xp[i];
        const float4* tp = reinterpret_cast<const float4*>(
            stab + i*256 + ((cd.x & 3)*4 + (cd.y & 3))*16 + hp*8);
        float4 t0 = tp[0], t1 = tp[1];
        a8[0]+=t0.x; a8[1]+=t0.y; a8[2]+=t0.z; a8[3]+=t0.w;
        a8[4]+=t1.x; a8[5]+=t1.y; a8[6]+=t1.z; a8[7]+=t1.w;
    }
#pragma unroll
    for (int k = 0; k < 8; k++) a8[k] = fmaxf(a8[k]*sc0 + pc0, 0.f);   // bn0 + relu

    // w_rank stage: pair-packed const weights
    u64 r2p0[16], r2p1[16];
#pragma unroll
    for (int hh = 0; hh < 2; hh++) {
        u64 b0p = pk(a8[hh*4+0], a8[hh*4+0]);
        u64 b1p = pk(a8[hh*4+1], a8[hh*4+1]);
        u64 b2p = pk(a8[hh*4+2], a8[hh*4+2]);
        u64 b3p = pk(a8[hh*4+3], a8[hh*4+3]);
#pragma unroll
        for (int oo = 0; oo < 16; oo++) {
            u64 e = sbasep[oo];
            const ulonglong2* wq = reinterpret_cast<const ulonglong2*>(&c_wrp[oo*8]);
            ulonglong2 wa = wq[0], wb = wq[1];
            e = ffma2(b0p, wa.x, e);
            e = ffma2(b1p, wa.y, e);
            e = ffma2(b2p, wb.x, e);
            e = ffma2(b3p, wb.y, e);
            float e0, e1; upk(e, e0, e1);
            u64 r = pk(fmaxf(e0, 0.f), fmaxf(e1, 0.f));
            if (hh == 0) r2p0[oo] = r; else r2p1[oo] = r;
        }
    }

    // w_h1 stage: output pairs (2o2, 2o2+1) for both h rows
    float s = 0.f, q = 0.f;
    size_t bh0 = (size_t)((c*4 + 2*hp)*16)*M + m;
#pragma unroll 2
    for (int o2 = 0; o2 < 16; o2++) {
        int oe = 2*o2, od = 2*o2 + 1;
        u64 aE0 = pk(c_bh1[oe], 0.f), aE1 = aE0;
        u64 aO0 = pk(c_bh1[od], 0.f), aO1 = aO0;
        const ulonglong2* wpe = reinterpret_cast<const ulonglong2*>(&c_wh1[oe*32]);
        const ulonglong2* wpo = reinterpret_cast<const ulonglong2*>(&c_wh1[od*32]);
#pragma unroll
        for (int i = 0; i < 8; i++) {
            ulonglong2 we = wpe[i], wo = wpo[i];
            aE0 = ffma2(r2p0[2*i], we.x, aE0); aE0 = ffma2(r2p0[2*i+1], we.y, aE0);
            aE1 = ffma2(r2p1[2*i], we.x, aE1); aE1 = ffma2(r2p1[2*i+1], we.y, aE1);
            aO0 = ffma2(r2p0[2*i], wo.x, aO0); aO0 = ffma2(r2p0[2*i+1], wo.y, aO0);
            aO1 = ffma2(r2p1[2*i], wo.x, aO1); aO1 = ffma2(r2p1[2*i+1], wo.y, aO1);
        }
        float e0l,e0h,e1l,e1h,o0l,o0h,o1l,o1h;
        upk(aE0,e0l,e0h); upk(aE1,e1l,e1h); upk(aO0,o0l,o0h); upk(aO1,o1l,o1h);
        float vE0 = e0l+e0h, vE1 = e1l+e1h, vO0 = o0l+o0h, vO1 = o1l+o1h;
        s += vE0 + vE1 + vO0 + vO1;
        q += vE0*vE0 + vE1*vE1 + vO0*vO0 + vO1*vO1;
        g_r3h[bh0 + (size_t)o2*M]        = __floats2half2_rn(vE0, vO0);   // h0
        g_r3h[bh0 + (size_t)(16+o2)*M]   = __floats2half2_rn(vE1, vO1);   // h0+1
    }
    for (int off = 16; off; off >>= 1) {
        s += __shfl_down_sync(0xffffffffu, s, off);
        q += __shfl_down_sync(0xffffffffu, q, off);
    }
    if ((t & 31) == 0) { atomicAdd(&red_s, s); atomicAdd(&red_q, q); }
    __syncthreads();
    if (t == 0) { atomicAdd(&g_bn1s[c], red_s); atomicAdd(&g_bn1q[c], red_q); }
}

// ---------------- k4: finalize BN1 + const path through w_h2, per-c blocks ----
__global__ void __launch_bounds__(32) k4(const float* __restrict__ bn1_g,
                                         const float* __restrict__ bn1_b,
                                         const float* __restrict__ w_h2,
                                         const float* __restrict__ b_h2) {
    __shared__ float swh2T[32*17];                    // transposed [i][o], padded
    __shared__ float rc3bn[32];
    int c = blockIdx.x, t = threadIdx.x;              // 32 threads = 1 warp
    for (int idx = t; idx < 512; idx += 32) {
        int o = idx >> 5, i = idx & 31;
        swh2T[i*17 + o] = w_h2[idx];
    }
    float n1   = (float)M * 11.0f * 32.0f;
    float mean = g_bn1s[c] / n1;
    float var  = g_bn1q[c] / n1 - mean*mean;
    float sc   = bn1_g[c] * rsqrtf(var + BNEPS);
    float sh   = bn1_b[c] - mean*sc;
    if (t == 0) { g_scale1[c] = sc; g_shift1[c] = sh; }
    rc3bn[t] = fmaxf(g_rc3[c*32 + t]*sc + sh, 0.f);
    __syncwarp();
    float acc = 0.f;
    bool act = t < 16;
    if (act) {
        acc = b_h2[t];
#pragma unroll
        for (int i = 0; i < 32; i++) acc += rc3bn[i] * swh2T[i*17 + t];
        g_rc4[c*16 + t] = acc;
    }
    float s = act ? acc : 0.f, q = act ? acc*acc : 0.f;
    for (int off = 16; off; off >>= 1) {
        s += __shfl_down_sync(0xffffffffu, s, off);
        q += __shfl_down_sync(0xffffffffu, q, off);
    }
    if (t == 0) {
        g_bn2s[c] = (float)(M*7)*s;                   // plain write; k5 adds after
        g_bn2q[c] = (float)(M*7)*q;
    }
}

// ---------------- k5: fused bn1+relu -> w_h2, BN2 sums (fp16 out, o-paired) ---
__global__ void __launch_bounds__(256, 3) k5() {
    __shared__ float red_s, red_q;
    int c = blockIdx.y, t = threadIdx.x;
    if (t == 0) { red_s = 0.f; red_q = 0.f; }
    __syncthreads();

    int hp = t >> 7;
    int m  = blockIdx.x*128 + (t & 127);
    float sc1 = g_scale1[c], sf1 = g_shift1[c];

    u64 yp0[16], yp1[16];
    size_t rb = (size_t)((c*4 + 2*hp)*16)*M + m;
#pragma unroll
    for (int i2 = 0; i2 < 16; i2++) {
        float2 f = __half22float2(g_r3h[rb + (size_t)i2*M]);
        yp0[i2] = pk(fmaxf(f.x*sc1 + sf1, 0.f), fmaxf(f.y*sc1 + sf1, 0.f));
    }
#pragma unroll
    for (int i2 = 0; i2 < 16; i2++) {
        float2 f = __half22float2(g_r3h[rb + (size_t)(16 + i2)*M]);
        yp1[i2] = pk(fmaxf(f.x*sc1 + sf1, 0.f), fmaxf(f.y*sc1 + sf1, 0.f));
    }

    float s = 0.f, q = 0.f;
    size_t wb = (size_t)(c*32)*M + m;
#pragma unroll 2
    for (int o2 = 0; o2 < 8; o2++) {
        int oe = 2*o2, od = 2*o2 + 1;
        u64 aE0 = pk(c_bh2[oe], 0.f), aE1 = aE0;
        u64 aO0 = pk(c_bh2[od], 0.f), aO1 = aO0;
        const ulonglong2* wpe = reinterpret_cast<const ulonglong2*>(&c_wh2[oe*32]);
        const ulonglong2* wpo = reinterpret_cast<const ulonglong2*>(&c_wh2[od*32]);
#pragma unroll
        for (int i = 0; i < 8; i++) {
            ulonglong2 we = wpe[i], wo = wpo[i];
            aE0 = ffma2(yp0[2*i], we.x, aE0); aE0 = ffma2(yp0[2*i+1], we.y, aE0);
            aE1 = ffma2(yp1[2*i], we.x, aE1); aE1 = ffma2(yp1[2*i+1], we.y, aE1);
            aO0 = ffma2(yp0[2*i], wo.x, aO0); aO0 = ffma2(yp0[2*i+1], wo.y, aO0);
            aO1 = ffma2(yp1[2*i], wo.x, aO1); aO1 = ffma2(yp1[2*i+1], wo.y, aO1);
        }
        float e0l,e0h,e1l,e1h,o0l,o0h,o1l,o1h;
        upk(aE0,e0l,e0h); upk(aE1,e1l,e1h); upk(aO0,o0l,o0h); upk(aO1,o1l,o1h);
        float vE0 = e0l+e0h, vE1 = e1l+e1h, vO0 = o0l+o0h, vO1 = o1l+o1h;
        s += vE0 + vE1 + vO0 + vO1;
        q += vE0*vE0 + vE1*vE1 + vO0*vO0 + vO1*vO1;
        g_r4h[wb + (size_t)((2*hp)*8   + o2)*M] = __floats2half2_rn(vE0, vO0);
        g_r4h[wb + (size_t)((2*hp+1)*8 + o2)*M] = __floats2half2_rn(vE1, vO1);
    }
    for (int off = 16; off; off >>= 1) {
        s += __shfl_down_sync(0xffffffffu, s, off);
        q += __shfl_down_sync(0xffffffffu, q, off);
    }
    if ((t & 31) == 0) { atomicAdd(&red_s, s); atomicAdd(&red_q, q); }
    __syncthreads();
    if (t == 0) { atomicAdd(&g_bn2s[c], red_s); atomicAdd(&g_bn2q[c], red_q); }
}

// ---------------- k6: finalize BN2, constant-row output contribution ----------
__global__ void k6(const float* __restrict__ bn2_g, const float* __restrict__ bn2_b,
                   const float* __restrict__ w_out, const float* __restrict__ b_out) {
    __shared__ float rc5[64*16];
    int t = threadIdx.x;                              // 288 = 9 warps
    if (t < 64) {
        float n2   = (float)M * 11.0f * 16.0f;
        float mean = g_bn2s[t] / n2;
        float var  = g_bn2q[t] / n2 - mean*mean;
        float sc   = bn2_g[t] * rsqrtf(var + BNEPS);
        float sh   = bn2_b[t] - mean*sc;
        g_scale2[t] = sc;
        g_shift2[t] = sh;
    }
    __syncthreads();
    for (int idx = t; idx < 1024; idx += 288) {
        int c = idx >> 4;
        rc5[idx] = fmaxf(g_rc4[idx]*g_scale2[c] + g_shift2[c], 0.f);
    }
    __syncthreads();
    int j = t >> 5, lane = t & 31;
    if (j < 9) {
        float acc = 0.f;
        for (int p = lane; p < 1024; p += 32) {
            int c = p >> 4, o = p & 15;
            float ws = 0.f;
#pragma unroll
            for (int h = 4; h < 11; h++) ws += w_out[j*11264 + c*176 + h*16 + o];
            acc += rc5[p]*ws;
        }
        for (int off = 16; off; off >>= 1) acc += __shfl_down_sync(0xffffffffu, acc, off);
        if (!lane) g_outconst[j] = b_out[j] + acc;
    }
}

// ---------------- k6b: seed output with constant part -------------------------
__global__ void k6b(float* __restrict__ out) {
    int idx = blockIdx.x*256 + threadIdx.x;
    if (idx < M*9) out[idx] = g_outconst[idx % 9];
}

// ---------------- k7: varying-feature GEMM (bn2+relu fused, fp16 in) ----------
__global__ void __launch_bounds__(256) k7(const float* __restrict__ w_out,
                                          float* __restrict__ out) {
    __shared__ u64 swe[9*32], swo[9*32];
    int t = threadIdx.x;
    int warp = t >> 5, lane = t & 31;
    int mbase = blockIdx.x*1024 + warp*128 + lane*4;
    int c0 = blockIdx.y*2;
    u64 accA[9], accB[9];
#pragma unroll
    for (int j = 0; j < 9; j++) { accA[j] = 0; accB[j] = 0; }
    for (int cc = 0; cc < 2; cc++) {
        int c = c0 + cc;
        __syncthreads();
        for (int idx = t; idx < 576; idx += 256) {
            int j = idx / 64, r = idx % 64, qq2 = r >> 1, eo = r & 1;
            int h = qq2 >> 3, o2 = qq2 & 7;
            float w = w_out[j*11264 + c*176 + h*16 + 2*o2 + eo];
            (eo ? swo : swe)[j*32 + qq2] = pk(w, w);
        }
        __syncthreads();
        float sc = g_scale2[c], sf = g_shift2[c];
        for (int qq2 = 0; qq2 < 32; qq2++) {
            const __half2* row = &g_r4h[(size_t)(c*32 + qq2)*M];
            uint2 ua = *reinterpret_cast<const uint2*>(row + mbase);
            uint2 ub = *reinterpret_cast<const uint2*>(row + mbase + 2);
            float2 f0 = __half22float2(*reinterpret_cast<__half2*>(&ua.x));
            float2 f1 = __half22float2(*reinterpret_cast<__half2*>(&ua.y));
            float2 f2 = __half22float2(*reinterpret_cast<__half2*>(&ub.x));
            float2 f3 = __half22float2(*reinterpret_cast<__half2*>(&ub.y));
            u64 yeA = pk(fmaxf(f0.x*sc+sf, 0.f), fmaxf(f1.x*sc+sf, 0.f));
            u64 yoA = pk(fmaxf(f0.y*sc+sf, 0.f), fmaxf(f1.y*sc+sf, 0.f));
            u64 yeB = pk(fmaxf(f2.x*sc+sf, 0.f), fmaxf(f3.x*sc+sf, 0.f));
            u64 yoB = pk(fmaxf(f2.y*sc+sf, 0.f), fmaxf(f3.y*sc+sf, 0.f));
#pragma unroll
            for (int j = 0; j < 9; j++) {
                u64 we = swe[j*32 + qq2], wo = swo[j*32 + qq2];
                accA[j] = ffma2(yeA, we, accA[j]);
                accA[j] = ffma2(yoA, wo, accA[j]);
                accB[j] = ffma2(yeB, we, accB[j]);
                accB[j] = ffma2(yoB, wo, accB[j]);
            }
        }
    }
#pragma unroll
    for (int j = 0; j < 9; j++) {
        float a0, a1, b0, b1;
        upk(accA[j], a0, a1);
        upk(accB[j], b0, b1);
        atomicAdd(&out[(size_t)mbase*9 + j],     a0);
        atomicAdd(&out[(size_t)(mbase+1)*9 + j], a1);
        atomicAdd(&out[(size_t)(mbase+2)*9 + j], b0);
        atomicAdd(&out[(size_t)(mbase+3)*9 + j], b1);
    }
}

// ---------------- launch ------------------------------------------------------
extern "C" void kernel_launch(void* const* d_in, const int* in_sizes, int n_in,
                              void* d_out, int out_size) {
    const int*   x      = (const int*)  d_in[0];
    const float* conv_w = (const float*)d_in[1];
    const float* conv_b = (const float*)d_in[2];
    const float* bn0_g  = (const float*)d_in[3];
    const float* bn0_b  = (const float*)d_in[4];
    const float* w_rank = (const float*)d_in[5];
    const float* b_rank = (const float*)d_in[6];
    const float* w_h1   = (const float*)d_in[7];
    const float* b_h1   = (const float*)d_in[8];
    const float* bn1_g  = (const float*)d_in[9];
    const float* bn1_b  = (const float*)d_in[10];
    const float* w_h2   = (const float*)d_in[11];
    const float* b_h2   = (const float*)d_in[12];
    const float* bn2_g  = (const float*)d_in[13];
    const float* bn2_b  = (const float*)d_in[14];
    const float* w_out  = (const float*)d_in[15];
    const float* b_out  = (const float*)d_in[16];
    float* out = (float*)d_out;

    kpack<<<3, 1024>>>(w_rank, b_rank, w_h1, b_h1, w_h2, b_h2);
    void* stage_ptr = nullptr;
    cudaGetSymbolAddress(&stage_ptr, g_stage);
    cudaMemcpyToSymbolAsync(c_all, stage_ptr, 2064*sizeof(float), 0,
                            cudaMemcpyDeviceToDevice, 0);

    ktable<<<84, 1024>>>(conv_w, x);
    kbn0k2<<<64, 256>>>(conv_b, bn0_g, bn0_b, w_rank, b_rank, w_h1, b_h1);
    k3<<<dim3(32, 64), 256>>>(x, conv_b);
    k4<<<64, 32>>>(bn1_g, bn1_b, w_h2, b_h2);
    k5<<<dim3(32, 64), 256>>>();
    k6<<<1, 288>>>(bn2_g, bn2_b, w_out, b_out);
    k6b<<<144, 256>>>(out);
    k7<<<dim3(4, 32), 256>>>(w_out, out);
}